// round 8
// baseline (speedup 1.0000x reference)
#include <cuda_runtime.h>
#include <cuda_bf16.h>
#include <cstdint>
#include <math.h>

#define BB 2
#define SS 2048
#define EE 1024
#define HH 16
#define DD 64
#define NQKV 3072

// ---------------------------------------------------------------------------
// Scratch (device globals — allocation-free)
// ---------------------------------------------------------------------------
__device__ __nv_bfloat16 g_xh[BB*SS*EE],  g_xl[BB*SS*EE];    // split x
__device__ __nv_bfloat16 g_wqh[EE*NQKV],  g_wql[EE*NQKV];    // split w_qkv
__device__ __nv_bfloat16 g_woh[EE*EE],    g_wol[EE*EE];      // split w_out
__device__ __nv_bfloat16 g_qh[BB*HH*SS*DD], g_ql[BB*HH*SS*DD];
__device__ __nv_bfloat16 g_kh[BB*HH*SS*DD], g_kl[BB*HH*SS*DD];
__device__ __nv_bfloat16 g_vh[BB*HH*SS*DD], g_vl[BB*HH*SS*DD];
__device__ __nv_bfloat16 g_oh[BB*SS*EE],    g_ol[BB*SS*EE];

// single TU-wide dynamic smem symbol (char) — cast per kernel
extern __shared__ __align__(16) char dynsmem[];

// ---------------------------------------------------------------------------
// PTX wrappers
// ---------------------------------------------------------------------------
__device__ __forceinline__ void ldsm4(unsigned r[4], uint32_t a) {
    asm volatile("ldmatrix.sync.aligned.m8n8.x4.shared.b16 {%0,%1,%2,%3}, [%4];\n"
                 : "=r"(r[0]), "=r"(r[1]), "=r"(r[2]), "=r"(r[3]) : "r"(a));
}
__device__ __forceinline__ void ldsm4t(unsigned r[4], uint32_t a) {
    asm volatile("ldmatrix.sync.aligned.m8n8.x4.trans.shared.b16 {%0,%1,%2,%3}, [%4];\n"
                 : "=r"(r[0]), "=r"(r[1]), "=r"(r[2]), "=r"(r[3]) : "r"(a));
}
__device__ __forceinline__ void mma_bf16(float c[4], const unsigned a[4], const unsigned b[2]) {
    asm volatile(
        "mma.sync.aligned.m16n8k16.row.col.f32.bf16.bf16.f32 "
        "{%0,%1,%2,%3}, {%4,%5,%6,%7}, {%8,%9}, {%0,%1,%2,%3};\n"
        : "+f"(c[0]), "+f"(c[1]), "+f"(c[2]), "+f"(c[3])
        : "r"(a[0]), "r"(a[1]), "r"(a[2]), "r"(a[3]), "r"(b[0]), "r"(b[1]));
}
__device__ __forceinline__ void cp16(uint32_t s, const void* g) {
    asm volatile("cp.async.cg.shared.global [%0], [%1], 16;\n" :: "r"(s), "l"(g));
}
__device__ __forceinline__ void cp_commit() {
    asm volatile("cp.async.commit_group;\n" ::: "memory");
}
template <int N>
__device__ __forceinline__ void cp_wait() {
    asm volatile("cp.async.wait_group %0;\n" :: "n"(N) : "memory");
}
__device__ __forceinline__ void split_pair(float x, float y, unsigned &hi, unsigned &lo) {
    __nv_bfloat162 h2 = __floats2bfloat162_rn(x, y);
    float xr = x - __bfloat162float(__low2bfloat16(h2));
    float yr = y - __bfloat162float(__high2bfloat16(h2));
    __nv_bfloat162 l2 = __floats2bfloat162_rn(xr, yr);
    hi = *reinterpret_cast<unsigned*>(&h2);
    lo = *reinterpret_cast<unsigned*>(&l2);
}
__device__ __forceinline__ uint32_t smem_u32(const void* p) {
    return (uint32_t)__cvta_generic_to_shared(p);
}

// ---------------------------------------------------------------------------
// Elementwise fp32 -> bf16 hi/lo split
// ---------------------------------------------------------------------------
__global__ __launch_bounds__(256) void split_kernel(const float* __restrict__ src,
                                                    __nv_bfloat16* __restrict__ dh,
                                                    __nv_bfloat16* __restrict__ dl,
                                                    int n4) {
    int i = blockIdx.x * 256 + threadIdx.x;
    if (i < n4) {
        float4 v = *(const float4*)(src + (size_t)i * 4);
        unsigned h0, l0, h1, l1;
        split_pair(v.x, v.y, h0, l0);
        split_pair(v.z, v.w, h1, l1);
        *(uint2*)(dh + (size_t)i * 4) = make_uint2(h0, h1);
        *(uint2*)(dl + (size_t)i * 4) = make_uint2(l0, l1);
    }
}

// ---------------------------------------------------------------------------
// bf16x3 GEMM, 3-stage cp.async ring, ONE sync per k-tile, term-major MMAs.
// C[M, NC] = A[M,1024] @ W[1024,NC].  BM=128, BN=128, BK=32, 8 warps,
// warp tile 32x64, 2 CTAs/SM.
// Stage layout (elems): [Ah 128*40 | Al 128*40 | Bh 32*136 | Bl 32*136]
// ---------------------------------------------------------------------------
#define ST_A 5120                   // 128*40 elems per hl
#define ST_B 4352                   // 32*136 elems per hl
#define ST_BYTES ((2 * ST_A + 2 * ST_B) * 2)   // 37888 B
#define G3_SMEM (3 * ST_BYTES)                  // 113664 B

template <int NC, bool SCATTER>
__global__ __launch_bounds__(256, 2) void mma_gemm3(const __nv_bfloat16* __restrict__ Ah_g,
                                                    const __nv_bfloat16* __restrict__ Al_g,
                                                    const __nv_bfloat16* __restrict__ Bh_g,
                                                    const __nv_bfloat16* __restrict__ Bl_g,
                                                    float* __restrict__ C) {
    char* smem = dynsmem;
    const int tid = threadIdx.x;
    const int lane = tid & 31, wid = tid >> 5;
    const int wm = (wid & 3) * 32, wn = (wid >> 2) * 64;
    const int m0 = blockIdx.y * 128, n0 = blockIdx.x * 128;

    const uint32_t uS = smem_u32(smem);
    const int lm_r = lane & 15, lm_c = (lane >> 4) * 8;
    const uint32_t aoff0 = ((wm + lm_r) * 40 + lm_c) * 2;
    const uint32_t boff0 = (lm_r * 136 + wn + lm_c) * 2;

    float acc[2][8][4];
#pragma unroll
    for (int i = 0; i < 2; i++)
#pragma unroll
        for (int j = 0; j < 8; j++)
#pragma unroll
            for (int q = 0; q < 4; q++) acc[i][j][q] = 0.0f;

    auto load_tile = [&](int slot, int k0) {
        uint32_t base = uS + slot * ST_BYTES;
#pragma unroll
        for (int i = 0; i < 2; i++) {
            int idx = tid + i * 256;              // 0..511
            int r = idx >> 2, c8 = (idx & 3) * 8; // r 0..127, c8 0..24
            cp16(base + (r * 40 + c8) * 2,
                 Ah_g + (size_t)(m0 + r) * EE + k0 + c8);
            cp16(base + ST_A * 2 + (r * 40 + c8) * 2,
                 Al_g + (size_t)(m0 + r) * EE + k0 + c8);
        }
        uint32_t bbase = uS + slot * ST_BYTES + 4 * ST_A;   // 2 hl * ST_A elems * 2B
#pragma unroll
        for (int i = 0; i < 2; i++) {
            int idx = tid + i * 256;
            int r = idx >> 4, c8 = (idx & 15) * 8; // r 0..31, c8 0..120
            cp16(bbase + (r * 136 + c8) * 2,
                 Bh_g + (size_t)(k0 + r) * NC + n0 + c8);
            cp16(bbase + ST_B * 2 + (r * 136 + c8) * 2,
                 Bl_g + (size_t)(k0 + r) * NC + n0 + c8);
        }
    };

    // prologue: 2 tiles in flight
    load_tile(0, 0);  cp_commit();
    load_tile(1, 32); cp_commit();

#pragma unroll 1
    for (int kt = 0; kt < 32; kt++) {
        const int slot = kt - (kt / 3) * 3;
        if (kt < 31) cp_wait<1>(); else cp_wait<0>();
        __syncthreads();   // all warps done with stage kt-1 -> safe to reload it

        if (kt + 2 < 32) {
            int ns = (kt + 2) - ((kt + 2) / 3) * 3;
            load_tile(ns, (kt + 2) * 32);
            cp_commit();
        }

        const uint32_t uAh = uS + slot * ST_BYTES;
        const uint32_t uAl = uAh + ST_A * 2;
        const uint32_t uBh = uS + slot * ST_BYTES + 4 * ST_A;
        const uint32_t uBl = uBh + ST_B * 2;

#pragma unroll
        for (int ks = 0; ks < 2; ks++) {
            const int kk = ks * 16;
            unsigned ah[2][4], al[2][4];
#pragma unroll
            for (int tm = 0; tm < 2; tm++) {
                uint32_t off = aoff0 + (tm * 16 * 40 + kk) * 2;
                ldsm4(ah[tm], uAh + off);
                ldsm4(al[tm], uAl + off);
            }
#pragma unroll
            for (int g = 0; g < 4; g++) {
                unsigned bh[4], bl[4];
                uint32_t off = boff0 + (kk * 136 + g * 16) * 2;
                ldsm4t(bh, uBh + off);
                ldsm4t(bl, uBl + off);
                // term-major: 4 independent accumulators per term (distance 4)
                mma_bf16(acc[0][2 * g],     ah[0], &bh[0]);
                mma_bf16(acc[0][2 * g + 1], ah[0], &bh[2]);
                mma_bf16(acc[1][2 * g],     ah[1], &bh[0]);
                mma_bf16(acc[1][2 * g + 1], ah[1], &bh[2]);
                mma_bf16(acc[0][2 * g],     ah[0], &bl[0]);
                mma_bf16(acc[0][2 * g + 1], ah[0], &bl[2]);
                mma_bf16(acc[1][2 * g],     ah[1], &bl[0]);
                mma_bf16(acc[1][2 * g + 1], ah[1], &bl[2]);
                mma_bf16(acc[0][2 * g],     al[0], &bh[0]);
                mma_bf16(acc[0][2 * g + 1], al[0], &bh[2]);
                mma_bf16(acc[1][2 * g],     al[1], &bh[0]);
                mma_bf16(acc[1][2 * g + 1], al[1], &bh[2]);
            }
        }
    }

    if (SCATTER) {
#pragma unroll
        for (int tm = 0; tm < 2; tm++)
#pragma unroll
            for (int nt = 0; nt < 8; nt++) {
                int f = n0 + wn + nt * 8 + (lane & 3) * 2;
                int cid = f >> 10;
                int hh = (f >> 6) & (HH - 1);
                int d = f & (DD - 1);
                float sc = (cid == 0) ? 0.125f : 1.0f;
                __nv_bfloat16* dh = (cid == 0) ? g_qh : (cid == 1) ? g_kh : g_vh;
                __nv_bfloat16* dl = (cid == 0) ? g_ql : (cid == 1) ? g_kl : g_vl;
#pragma unroll
                for (int half = 0; half < 2; half++) {
                    int row = m0 + wm + tm * 16 + (lane >> 2) + half * 8;
                    int b = row >> 11, s = row & (SS - 1);
                    size_t off = ((size_t)((b * HH + hh) * SS + s)) * DD + d;
                    unsigned hi, lo;
                    split_pair(acc[tm][nt][half * 2] * sc,
                               acc[tm][nt][half * 2 + 1] * sc, hi, lo);
                    *(unsigned*)&dh[off] = hi;
                    *(unsigned*)&dl[off] = lo;
                }
            }
    } else {
#pragma unroll
        for (int tm = 0; tm < 2; tm++)
#pragma unroll
            for (int nt = 0; nt < 8; nt++) {
                int col = n0 + wn + nt * 8 + (lane & 3) * 2;
#pragma unroll
                for (int half = 0; half < 2; half++) {
                    int row = m0 + wm + tm * 16 + (lane >> 2) + half * 8;
                    float2 v = make_float2(acc[tm][nt][half * 2],
                                           acc[tm][nt][half * 2 + 1]);
                    *(float2*)&C[(size_t)row * NC + col] = v;
                }
            }
    }
}

// ---------------------------------------------------------------------------
// Flash attention, bf16x3 mma, cp.async double-buffered K/V, 2 CTAs/SM.
// Term-major MMA issue (distance 2) — bitwise-identical math to round 5.
// ---------------------------------------------------------------------------
#define AT_Q 9216            // 128*72
#define AT_T 4608            // 64*72
#define AT_KV (2 * AT_Q)

__global__ __launch_bounds__(256, 2) void attn_mma2() {
    __nv_bfloat16* smem = (__nv_bfloat16*)dynsmem;
    const int tid = threadIdx.x, lane = tid & 31, w = tid >> 5;
    const int q0 = blockIdx.x * 128, h = blockIdx.y, b = blockIdx.z;
    const size_t hb = (size_t)(b * HH + h) * SS * DD;

    const uint32_t uS = smem_u32(smem);
    const uint32_t uQh = uS, uQl = uS + AT_Q * 2;

    const int lm_r = lane & 15, lm_c = (lane >> 4) * 8;
    const int bn_r = (lane & 7) + (lane >> 4) * 8;
    const int bn_c = ((lane >> 3) & 1) * 8;

    auto kv_base = [&](int buf, int t) -> uint32_t {
        return uS + (AT_KV + (buf * 4 + t) * AT_T) * 2;
    };

    auto load_kv = [&](int buf, int kv) {
        const __nv_bfloat16* s0 = g_kh + hb + (size_t)kv * DD;
        const __nv_bfloat16* s1 = g_kl + hb + (size_t)kv * DD;
        const __nv_bfloat16* s2 = g_vh + hb + (size_t)kv * DD;
        const __nv_bfloat16* s3 = g_vl + hb + (size_t)kv * DD;
#pragma unroll
        for (int i = 0; i < 2; i++) {
            int idx = tid + i * 256;
            int r = idx >> 3, c8 = (idx & 7) * 8;
            uint32_t so = (r * 72 + c8) * 2;
            int go = r * DD + c8;
            cp16(kv_base(buf, 0) + so, s0 + go);
            cp16(kv_base(buf, 1) + so, s1 + go);
            cp16(kv_base(buf, 2) + so, s2 + go);
            cp16(kv_base(buf, 3) + so, s3 + go);
        }
    };

#pragma unroll
    for (int i = 0; i < 4; i++) {
        int idx = tid + i * 256;
        int r = idx >> 3, c8 = (idx & 7) * 8;
        uint32_t so = (r * 72 + c8) * 2;
        size_t go = hb + (size_t)(q0 + r) * DD + c8;
        cp16(uQh + so, g_qh + go);
        cp16(uQl + so, g_ql + go);
    }
    load_kv(0, 0);
    cp_commit();

    float m1 = -1.0e30f, m2 = -1.0e30f, l1 = 0.0f, l2 = 0.0f;
    float oacc[8][4];
#pragma unroll
    for (int j = 0; j < 8; j++)
#pragma unroll
        for (int q = 0; q < 4; q++) oacc[j][q] = 0.0f;

#pragma unroll 1
    for (int ti = 0; ti < 32; ti++) {
        const int buf = ti & 1;
        if (ti + 1 < 32) load_kv(buf ^ 1, (ti + 1) * 64);
        cp_commit();
        if (ti + 1 < 32) cp_wait<1>(); else cp_wait<0>();
        __syncthreads();

        const uint32_t uKh = kv_base(buf, 0), uKl = kv_base(buf, 1);
        const uint32_t uVh = kv_base(buf, 2), uVl = kv_base(buf, 3);

        float sacc[8][4];
#pragma unroll
        for (int j = 0; j < 8; j++)
#pragma unroll
            for (int q = 0; q < 4; q++) sacc[j][q] = 0.0f;

#pragma unroll
        for (int kt = 0; kt < 4; kt++) {
            unsigned ah[4], al[4];
            uint32_t qoff = ((w * 16 + lm_r) * 72 + kt * 16 + lm_c) * 2;
            ldsm4(ah, uQh + qoff);
            ldsm4(al, uQl + qoff);
#pragma unroll
            for (int g = 0; g < 4; g++) {
                unsigned bh[4], bl[4];
                uint32_t koff = ((g * 16 + bn_r) * 72 + kt * 16 + bn_c) * 2;
                ldsm4(bh, uKh + koff);
                ldsm4(bl, uKl + koff);
                // term-major (distance 2)
                mma_bf16(sacc[2 * g],     ah, &bh[0]);
                mma_bf16(sacc[2 * g + 1], ah, &bh[2]);
                mma_bf16(sacc[2 * g],     ah, &bl[0]);
                mma_bf16(sacc[2 * g + 1], ah, &bl[2]);
                mma_bf16(sacc[2 * g],     al, &bh[0]);
                mma_bf16(sacc[2 * g + 1], al, &bh[2]);
            }
        }

        float mx1 = -1.0e30f, mx2 = -1.0e30f;
#pragma unroll
        for (int nt = 0; nt < 8; nt++) {
            mx1 = fmaxf(mx1, fmaxf(sacc[nt][0], sacc[nt][1]));
            mx2 = fmaxf(mx2, fmaxf(sacc[nt][2], sacc[nt][3]));
        }
#pragma unroll
        for (int off = 1; off <= 2; off <<= 1) {
            mx1 = fmaxf(mx1, __shfl_xor_sync(0xffffffffu, mx1, off));
            mx2 = fmaxf(mx2, __shfl_xor_sync(0xffffffffu, mx2, off));
        }
        float mn1 = fmaxf(m1, mx1), mn2 = fmaxf(m2, mx2);
        float fac1 = __expf(m1 - mn1), fac2 = __expf(m2 - mn2);
        float rs1 = 0.0f, rs2 = 0.0f;
#pragma unroll
        for (int nt = 0; nt < 8; nt++) {
            sacc[nt][0] = __expf(sacc[nt][0] - mn1);
            sacc[nt][1] = __expf(sacc[nt][1] - mn1);
            sacc[nt][2] = __expf(sacc[nt][2] - mn2);
            sacc[nt][3] = __expf(sacc[nt][3] - mn2);
            rs1 += sacc[nt][0] + sacc[nt][1];
            rs2 += sacc[nt][2] + sacc[nt][3];
        }
#pragma unroll
        for (int off = 1; off <= 2; off <<= 1) {
            rs1 += __shfl_xor_sync(0xffffffffu, rs1, off);
            rs2 += __shfl_xor_sync(0xffffffffu, rs2, off);
        }
        l1 = l1 * fac1 + rs1;
        l2 = l2 * fac2 + rs2;
        m1 = mn1;
        m2 = mn2;
#pragma unroll
        for (int nt = 0; nt < 8; nt++) {
            oacc[nt][0] *= fac1;
            oacc[nt][1] *= fac1;
            oacc[nt][2] *= fac2;
            oacc[nt][3] *= fac2;
        }

        unsigned ph[4][4], pl[4][4];
#pragma unroll
        for (int kt = 0; kt < 4; kt++) {
            split_pair(sacc[2 * kt][0],     sacc[2 * kt][1],     ph[kt][0], pl[kt][0]);
            split_pair(sacc[2 * kt][2],     sacc[2 * kt][3],     ph[kt][1], pl[kt][1]);
            split_pair(sacc[2 * kt + 1][0], sacc[2 * kt + 1][1], ph[kt][2], pl[kt][2]);
            split_pair(sacc[2 * kt + 1][2], sacc[2 * kt + 1][3], ph[kt][3], pl[kt][3]);
        }

#pragma unroll
        for (int kt = 0; kt < 4; kt++) {
#pragma unroll
            for (int dg = 0; dg < 4; dg++) {
                unsigned vh[4], vl[4];
                uint32_t voff = ((kt * 16 + lm_r) * 72 + dg * 16 + lm_c) * 2;
                ldsm4t(vh, uVh + voff);
                ldsm4t(vl, uVl + voff);
                // term-major (distance 2)
                mma_bf16(oacc[2 * dg],     ph[kt], &vh[0]);
                mma_bf16(oacc[2 * dg + 1], ph[kt], &vh[2]);
                mma_bf16(oacc[2 * dg],     ph[kt], &vl[0]);
                mma_bf16(oacc[2 * dg + 1], ph[kt], &vl[2]);
                mma_bf16(oacc[2 * dg],     pl[kt], &vh[0]);
                mma_bf16(oacc[2 * dg + 1], pl[kt], &vh[2]);
            }
        }
        __syncthreads();
    }

    float inv1 = 1.0f / l1, inv2 = 1.0f / l2;
    int r1 = q0 + w * 16 + (lane >> 2);
#pragma unroll
    for (int nt = 0; nt < 8; nt++) {
        int d = nt * 8 + (lane & 3) * 2;
        unsigned hi, lo;
        split_pair(oacc[nt][0] * inv1, oacc[nt][1] * inv1, hi, lo);
        size_t off = ((size_t)(b * SS + r1)) * EE + h * DD + d;
        *(unsigned*)&g_oh[off] = hi;
        *(unsigned*)&g_ol[off] = lo;
        split_pair(oacc[nt][2] * inv2, oacc[nt][3] * inv2, hi, lo);
        off = ((size_t)(b * SS + r1 + 8)) * EE + h * DD + d;
        *(unsigned*)&g_oh[off] = hi;
        *(unsigned*)&g_ol[off] = lo;
    }
}

// ---------------------------------------------------------------------------
extern "C" void kernel_launch(void* const* d_in, const int* in_sizes, int n_in,
                              void* d_out, int out_size) {
    const float* x = (const float*)d_in[0];      // (B, S, E)
    const float* w_qkv = (const float*)d_in[1];  // (E, 3E)
    const float* w_out = (const float*)d_in[2];  // (E, E)
    float* out = (float*)d_out;                  // (B, S, E)

    __nv_bfloat16 *p_xh, *p_xl, *p_wqh, *p_wql, *p_woh, *p_wol, *p_oh, *p_ol;
    cudaGetSymbolAddress((void**)&p_xh, g_xh);
    cudaGetSymbolAddress((void**)&p_xl, g_xl);
    cudaGetSymbolAddress((void**)&p_wqh, g_wqh);
    cudaGetSymbolAddress((void**)&p_wql, g_wql);
    cudaGetSymbolAddress((void**)&p_woh, g_woh);
    cudaGetSymbolAddress((void**)&p_wol, g_wol);
    cudaGetSymbolAddress((void**)&p_oh, g_oh);
    cudaGetSymbolAddress((void**)&p_ol, g_ol);

    // 0) split inputs once
    split_kernel<<<(BB*SS*EE/4 + 255) / 256, 256>>>(x, p_xh, p_xl, BB*SS*EE/4);
    split_kernel<<<(EE*NQKV/4 + 255) / 256, 256>>>(w_qkv, p_wqh, p_wql, EE*NQKV/4);
    split_kernel<<<(EE*EE/4 + 255) / 256, 256>>>(w_out, p_woh, p_wol, EE*EE/4);

    // 1) QKV projection, scatter Q/K/V hi/lo (Q pre-scaled)
    cudaFuncSetAttribute(mma_gemm3<NQKV, true>,
                         cudaFuncAttributeMaxDynamicSharedMemorySize, G3_SMEM);
    mma_gemm3<NQKV, true><<<dim3(NQKV / 128, (BB * SS) / 128), 256, G3_SMEM>>>(
        p_xh, p_xl, p_wqh, p_wql, nullptr);

    // 2) Flash attention
    const int attn_smem = (AT_KV + 8 * AT_T) * (int)sizeof(__nv_bfloat16);
    cudaFuncSetAttribute(attn_mma2, cudaFuncAttributeMaxDynamicSharedMemorySize,
                         attn_smem);
    attn_mma2<<<dim3(SS / 128, HH, BB), 256, attn_smem>>>();

    // 3) Output projection
    cudaFuncSetAttribute(mma_gemm3<EE, false>,
                         cudaFuncAttributeMaxDynamicSharedMemorySize, G3_SMEM);
    mma_gemm3<EE, false><<<dim3(EE / 128, (BB * SS) / 128), 256, G3_SMEM>>>(
        p_oh, p_ol, p_woh, p_wol, out);
}

// round 9
// speedup vs baseline: 1.4023x; 1.4023x over previous
#include <cuda_runtime.h>
#include <cuda_fp16.h>
#include <cstdint>
#include <math.h>

#define BB 2
#define SS 2048
#define EE 1024
#define HH 16
#define DD 64
#define NQKV 3072

// ---------------------------------------------------------------------------
// Scratch (device globals — allocation-free). fp16 hi/lo pairs; B-side
// consumers read only the hi part.
// ---------------------------------------------------------------------------
__device__ __half g_xh[BB*SS*EE],  g_xl[BB*SS*EE];    // split x
__device__ __half g_wqh[EE*NQKV],  g_wql[EE*NQKV];    // split w_qkv (lo unused)
__device__ __half g_woh[EE*EE],    g_wol[EE*EE];      // split w_out (lo unused)
__device__ __half g_qh[BB*HH*SS*DD], g_ql[BB*HH*SS*DD];
__device__ __half g_kh[BB*HH*SS*DD], g_kl[BB*HH*SS*DD];  // kl unused
__device__ __half g_vh[BB*HH*SS*DD], g_vl[BB*HH*SS*DD];  // vl unused
__device__ __half g_oh[BB*SS*EE],    g_ol[BB*SS*EE];

// single TU-wide dynamic smem symbol (char) — cast per kernel
extern __shared__ __align__(16) char dynsmem[];

// ---------------------------------------------------------------------------
// PTX wrappers
// ---------------------------------------------------------------------------
__device__ __forceinline__ void ldsm4(unsigned r[4], uint32_t a) {
    asm volatile("ldmatrix.sync.aligned.m8n8.x4.shared.b16 {%0,%1,%2,%3}, [%4];\n"
                 : "=r"(r[0]), "=r"(r[1]), "=r"(r[2]), "=r"(r[3]) : "r"(a));
}
__device__ __forceinline__ void ldsm4t(unsigned r[4], uint32_t a) {
    asm volatile("ldmatrix.sync.aligned.m8n8.x4.trans.shared.b16 {%0,%1,%2,%3}, [%4];\n"
                 : "=r"(r[0]), "=r"(r[1]), "=r"(r[2]), "=r"(r[3]) : "r"(a));
}
__device__ __forceinline__ void mma_f16(float c[4], const unsigned a[4], const unsigned b[2]) {
    asm volatile(
        "mma.sync.aligned.m16n8k16.row.col.f32.f16.f16.f32 "
        "{%0,%1,%2,%3}, {%4,%5,%6,%7}, {%8,%9}, {%0,%1,%2,%3};\n"
        : "+f"(c[0]), "+f"(c[1]), "+f"(c[2]), "+f"(c[3])
        : "r"(a[0]), "r"(a[1]), "r"(a[2]), "r"(a[3]), "r"(b[0]), "r"(b[1]));
}
__device__ __forceinline__ void cp16(uint32_t s, const void* g) {
    asm volatile("cp.async.cg.shared.global [%0], [%1], 16;\n" :: "r"(s), "l"(g));
}
__device__ __forceinline__ void cp_commit() {
    asm volatile("cp.async.commit_group;\n" ::: "memory");
}
template <int N>
__device__ __forceinline__ void cp_wait() {
    asm volatile("cp.async.wait_group %0;\n" :: "n"(N) : "memory");
}
// split (x,y) fp32 pair into packed fp16x2 hi and lo (residual) words
__device__ __forceinline__ void split_pair_h(float x, float y, unsigned &hi, unsigned &lo) {
    __half2 h2 = __floats2half2_rn(x, y);
    float xr = x - __half2float(__low2half(h2));
    float yr = y - __half2float(__high2half(h2));
    __half2 l2 = __floats2half2_rn(xr, yr);
    hi = *reinterpret_cast<unsigned*>(&h2);
    lo = *reinterpret_cast<unsigned*>(&l2);
}
__device__ __forceinline__ uint32_t smem_u32(const void* p) {
    return (uint32_t)__cvta_generic_to_shared(p);
}

// ---------------------------------------------------------------------------
// Elementwise fp32 -> fp16 hi/lo split
// ---------------------------------------------------------------------------
__global__ __launch_bounds__(256) void split_kernel(const float* __restrict__ src,
                                                    __half* __restrict__ dh,
                                                    __half* __restrict__ dl,
                                                    int n4) {
    int i = blockIdx.x * 256 + threadIdx.x;
    if (i < n4) {
        float4 v = *(const float4*)(src + (size_t)i * 4);
        unsigned h0, l0, h1, l1;
        split_pair_h(v.x, v.y, h0, l0);
        split_pair_h(v.z, v.w, h1, l1);
        *(uint2*)(dh + (size_t)i * 4) = make_uint2(h0, h1);
        *(uint2*)(dl + (size_t)i * 4) = make_uint2(l0, l1);
    }
}

// ---------------------------------------------------------------------------
// fp16x2 GEMM: C[M, NC] = A[M,1024](hi+lo) @ W[1024,NC](hi only)
// BM=128, BN=128, BK=32, 8 warps, warp tile 32x64, 2 CTAs/SM.
// 3-stage cp.async ring, one sync per k-tile.
// Stage layout (elems): [Ah 128*40 | Al 128*40 | Bh 32*136]
// ---------------------------------------------------------------------------
#define ST_A 5120                              // 128*40 elems per hl
#define ST_B 4352                              // 32*136 elems
#define ST_BYTES ((2 * ST_A + ST_B) * 2)       // 29184 B
#define G3_SMEM (3 * ST_BYTES)                 // 87552 B

template <int NC, bool SCATTER>
__global__ __launch_bounds__(256, 2) void mma_gemm3(const __half* __restrict__ Ah_g,
                                                    const __half* __restrict__ Al_g,
                                                    const __half* __restrict__ Bh_g,
                                                    float* __restrict__ C) {
    char* smem = dynsmem;
    const int tid = threadIdx.x;
    const int lane = tid & 31, wid = tid >> 5;
    const int wm = (wid & 3) * 32, wn = (wid >> 2) * 64;
    const int m0 = blockIdx.y * 128, n0 = blockIdx.x * 128;

    const uint32_t uS = smem_u32(smem);
    const int lm_r = lane & 15, lm_c = (lane >> 4) * 8;
    const uint32_t aoff0 = ((wm + lm_r) * 40 + lm_c) * 2;
    const uint32_t boff0 = (lm_r * 136 + wn + lm_c) * 2;

    float acc[2][8][4];
#pragma unroll
    for (int i = 0; i < 2; i++)
#pragma unroll
        for (int j = 0; j < 8; j++)
#pragma unroll
            for (int q = 0; q < 4; q++) acc[i][j][q] = 0.0f;

    auto load_tile = [&](int slot, int k0) {
        uint32_t base = uS + slot * ST_BYTES;
#pragma unroll
        for (int i = 0; i < 2; i++) {
            int idx = tid + i * 256;              // 0..511
            int r = idx >> 2, c8 = (idx & 3) * 8; // r 0..127, c8 0..24
            cp16(base + (r * 40 + c8) * 2,
                 Ah_g + (size_t)(m0 + r) * EE + k0 + c8);
            cp16(base + ST_A * 2 + (r * 40 + c8) * 2,
                 Al_g + (size_t)(m0 + r) * EE + k0 + c8);
        }
        uint32_t bbase = uS + slot * ST_BYTES + 4 * ST_A;  // after 2 hl A planes
#pragma unroll
        for (int i = 0; i < 2; i++) {
            int idx = tid + i * 256;
            int r = idx >> 4, c8 = (idx & 15) * 8; // r 0..31, c8 0..120
            cp16(bbase + (r * 136 + c8) * 2,
                 Bh_g + (size_t)(k0 + r) * NC + n0 + c8);
        }
    };

    load_tile(0, 0);  cp_commit();
    load_tile(1, 32); cp_commit();

#pragma unroll 1
    for (int kt = 0; kt < 32; kt++) {
        const int slot = kt - (kt / 3) * 3;
        if (kt < 31) cp_wait<1>(); else cp_wait<0>();
        __syncthreads();

        if (kt + 2 < 32) {
            int ns = (kt + 2) - ((kt + 2) / 3) * 3;
            load_tile(ns, (kt + 2) * 32);
            cp_commit();
        }

        const uint32_t uAh = uS + slot * ST_BYTES;
        const uint32_t uAl = uAh + ST_A * 2;
        const uint32_t uBh = uS + slot * ST_BYTES + 4 * ST_A;

#pragma unroll
        for (int ks = 0; ks < 2; ks++) {
            const int kk = ks * 16;
            unsigned ah[2][4], al[2][4];
#pragma unroll
            for (int tm = 0; tm < 2; tm++) {
                uint32_t off = aoff0 + (tm * 16 * 40 + kk) * 2;
                ldsm4(ah[tm], uAh + off);
                ldsm4(al[tm], uAl + off);
            }
#pragma unroll
            for (int g = 0; g < 4; g++) {
                unsigned bh[4];
                uint32_t off = boff0 + (kk * 136 + g * 16) * 2;
                ldsm4t(bh, uBh + off);
                // term-major, 4 independent accumulators per term
                mma_f16(acc[0][2 * g],     ah[0], &bh[0]);
                mma_f16(acc[0][2 * g + 1], ah[0], &bh[2]);
                mma_f16(acc[1][2 * g],     ah[1], &bh[0]);
                mma_f16(acc[1][2 * g + 1], ah[1], &bh[2]);
                mma_f16(acc[0][2 * g],     al[0], &bh[0]);
                mma_f16(acc[0][2 * g + 1], al[0], &bh[2]);
                mma_f16(acc[1][2 * g],     al[1], &bh[0]);
                mma_f16(acc[1][2 * g + 1], al[1], &bh[2]);
            }
        }
    }

    if (SCATTER) {
#pragma unroll
        for (int tm = 0; tm < 2; tm++)
#pragma unroll
            for (int nt = 0; nt < 8; nt++) {
                int f = n0 + wn + nt * 8 + (lane & 3) * 2;
                int cid = f >> 10;
                int hh = (f >> 6) & (HH - 1);
                int d = f & (DD - 1);
                float sc = (cid == 0) ? 0.125f : 1.0f;
                __half* dh = (cid == 0) ? g_qh : (cid == 1) ? g_kh : g_vh;
                __half* dl = (cid == 0) ? g_ql : (cid == 1) ? g_kl : g_vl;
#pragma unroll
                for (int half = 0; half < 2; half++) {
                    int row = m0 + wm + tm * 16 + (lane >> 2) + half * 8;
                    int b = row >> 11, s = row & (SS - 1);
                    size_t off = ((size_t)((b * HH + hh) * SS + s)) * DD + d;
                    unsigned hi, lo;
                    split_pair_h(acc[tm][nt][half * 2] * sc,
                                 acc[tm][nt][half * 2 + 1] * sc, hi, lo);
                    *(unsigned*)&dh[off] = hi;
                    *(unsigned*)&dl[off] = lo;
                }
            }
    } else {
#pragma unroll
        for (int tm = 0; tm < 2; tm++)
#pragma unroll
            for (int nt = 0; nt < 8; nt++) {
                int col = n0 + wn + nt * 8 + (lane & 3) * 2;
#pragma unroll
                for (int half = 0; half < 2; half++) {
                    int row = m0 + wm + tm * 16 + (lane >> 2) + half * 8;
                    float2 v = make_float2(acc[tm][nt][half * 2],
                                           acc[tm][nt][half * 2 + 1]);
                    *(float2*)&C[(size_t)row * NC + col] = v;
                }
            }
    }
}

// ---------------------------------------------------------------------------
// Flash attention, fp16x2 mma. Q split hi/lo; K, V single fp16.
// CTA = (b, h, 128 q rows), 8 warps, kv tiles of 64, double-buffered,
// 2 CTAs/SM.
// ---------------------------------------------------------------------------
#define AT_Q 9216            // 128*72 elems
#define AT_T 4608            // 64*72 elems
#define AT_KV (2 * AT_Q)

__global__ __launch_bounds__(256, 2) void attn_mma2() {
    __half* smem = (__half*)dynsmem;
    const int tid = threadIdx.x, lane = tid & 31, w = tid >> 5;
    const int q0 = blockIdx.x * 128, h = blockIdx.y, b = blockIdx.z;
    const size_t hb = (size_t)(b * HH + h) * SS * DD;

    const uint32_t uS = smem_u32(smem);
    const uint32_t uQh = uS, uQl = uS + AT_Q * 2;

    const int lm_r = lane & 15, lm_c = (lane >> 4) * 8;
    const int bn_r = (lane & 7) + (lane >> 4) * 8;
    const int bn_c = ((lane >> 3) & 1) * 8;

    // buf layout: [Kh | Vh] per buffer
    auto kv_base = [&](int buf, int t) -> uint32_t {
        return uS + (AT_KV + (buf * 2 + t) * AT_T) * 2;
    };

    auto load_kv = [&](int buf, int kv) {
        const __half* s0 = g_kh + hb + (size_t)kv * DD;
        const __half* s1 = g_vh + hb + (size_t)kv * DD;
#pragma unroll
        for (int i = 0; i < 2; i++) {
            int idx = tid + i * 256;
            int r = idx >> 3, c8 = (idx & 7) * 8;
            uint32_t so = (r * 72 + c8) * 2;
            int go = r * DD + c8;
            cp16(kv_base(buf, 0) + so, s0 + go);
            cp16(kv_base(buf, 1) + so, s1 + go);
        }
    };

#pragma unroll
    for (int i = 0; i < 4; i++) {
        int idx = tid + i * 256;
        int r = idx >> 3, c8 = (idx & 7) * 8;
        uint32_t so = (r * 72 + c8) * 2;
        size_t go = hb + (size_t)(q0 + r) * DD + c8;
        cp16(uQh + so, g_qh + go);
        cp16(uQl + so, g_ql + go);
    }
    load_kv(0, 0);
    cp_commit();

    float m1 = -1.0e30f, m2 = -1.0e30f, l1 = 0.0f, l2 = 0.0f;
    float oacc[8][4];
#pragma unroll
    for (int j = 0; j < 8; j++)
#pragma unroll
        for (int q = 0; q < 4; q++) oacc[j][q] = 0.0f;

#pragma unroll 1
    for (int ti = 0; ti < 32; ti++) {
        const int buf = ti & 1;
        if (ti + 1 < 32) load_kv(buf ^ 1, (ti + 1) * 64);
        cp_commit();
        if (ti + 1 < 32) cp_wait<1>(); else cp_wait<0>();
        __syncthreads();

        const uint32_t uKh = kv_base(buf, 0);
        const uint32_t uVh = kv_base(buf, 1);

        // S = Q @ K^T (scale folded into Q); Q split, K single
        float sacc[8][4];
#pragma unroll
        for (int j = 0; j < 8; j++)
#pragma unroll
            for (int q = 0; q < 4; q++) sacc[j][q] = 0.0f;

#pragma unroll
        for (int kt = 0; kt < 4; kt++) {
            unsigned ah[4], al[4];
            uint32_t qoff = ((w * 16 + lm_r) * 72 + kt * 16 + lm_c) * 2;
            ldsm4(ah, uQh + qoff);
            ldsm4(al, uQl + qoff);
#pragma unroll
            for (int g = 0; g < 4; g++) {
                unsigned bh[4];
                uint32_t koff = ((g * 16 + bn_r) * 72 + kt * 16 + bn_c) * 2;
                ldsm4(bh, uKh + koff);
                // term-major (distance 2)
                mma_f16(sacc[2 * g],     ah, &bh[0]);
                mma_f16(sacc[2 * g + 1], ah, &bh[2]);
                mma_f16(sacc[2 * g],     al, &bh[0]);
                mma_f16(sacc[2 * g + 1], al, &bh[2]);
            }
        }

        // Online softmax
        float mx1 = -1.0e30f, mx2 = -1.0e30f;
#pragma unroll
        for (int nt = 0; nt < 8; nt++) {
            mx1 = fmaxf(mx1, fmaxf(sacc[nt][0], sacc[nt][1]));
            mx2 = fmaxf(mx2, fmaxf(sacc[nt][2], sacc[nt][3]));
        }
#pragma unroll
        for (int off = 1; off <= 2; off <<= 1) {
            mx1 = fmaxf(mx1, __shfl_xor_sync(0xffffffffu, mx1, off));
            mx2 = fmaxf(mx2, __shfl_xor_sync(0xffffffffu, mx2, off));
        }
        float mn1 = fmaxf(m1, mx1), mn2 = fmaxf(m2, mx2);
        float fac1 = __expf(m1 - mn1), fac2 = __expf(m2 - mn2);
        float rs1 = 0.0f, rs2 = 0.0f;
#pragma unroll
        for (int nt = 0; nt < 8; nt++) {
            sacc[nt][0] = __expf(sacc[nt][0] - mn1);
            sacc[nt][1] = __expf(sacc[nt][1] - mn1);
            sacc[nt][2] = __expf(sacc[nt][2] - mn2);
            sacc[nt][3] = __expf(sacc[nt][3] - mn2);
            rs1 += sacc[nt][0] + sacc[nt][1];
            rs2 += sacc[nt][2] + sacc[nt][3];
        }
#pragma unroll
        for (int off = 1; off <= 2; off <<= 1) {
            rs1 += __shfl_xor_sync(0xffffffffu, rs1, off);
            rs2 += __shfl_xor_sync(0xffffffffu, rs2, off);
        }
        l1 = l1 * fac1 + rs1;
        l2 = l2 * fac2 + rs2;
        m1 = mn1;
        m2 = mn2;
#pragma unroll
        for (int nt = 0; nt < 8; nt++) {
            oacc[nt][0] *= fac1;
            oacc[nt][1] *= fac1;
            oacc[nt][2] *= fac2;
            oacc[nt][3] *= fac2;
        }

        // P fragments (hi/lo fp16) straight from sacc registers
        unsigned ph[4][4], pl[4][4];
#pragma unroll
        for (int kt = 0; kt < 4; kt++) {
            split_pair_h(sacc[2 * kt][0],     sacc[2 * kt][1],     ph[kt][0], pl[kt][0]);
            split_pair_h(sacc[2 * kt][2],     sacc[2 * kt][3],     ph[kt][1], pl[kt][1]);
            split_pair_h(sacc[2 * kt + 1][0], sacc[2 * kt + 1][1], ph[kt][2], pl[kt][2]);
            split_pair_h(sacc[2 * kt + 1][2], sacc[2 * kt + 1][3], ph[kt][3], pl[kt][3]);
        }

        // O += P @ V  (P split, V single)
#pragma unroll
        for (int kt = 0; kt < 4; kt++) {
#pragma unroll
            for (int dg = 0; dg < 4; dg++) {
                unsigned vh[4];
                uint32_t voff = ((kt * 16 + lm_r) * 72 + dg * 16 + lm_c) * 2;
                ldsm4t(vh, uVh + voff);
                mma_f16(oacc[2 * dg],     ph[kt], &vh[0]);
                mma_f16(oacc[2 * dg + 1], ph[kt], &vh[2]);
                mma_f16(oacc[2 * dg],     pl[kt], &vh[0]);
                mma_f16(oacc[2 * dg + 1], pl[kt], &vh[2]);
            }
        }
        __syncthreads();
    }

    // normalize + store O hi/lo
    float inv1 = 1.0f / l1, inv2 = 1.0f / l2;
    int r1 = q0 + w * 16 + (lane >> 2);
#pragma unroll
    for (int nt = 0; nt < 8; nt++) {
        int d = nt * 8 + (lane & 3) * 2;
        unsigned hi, lo;
        split_pair_h(oacc[nt][0] * inv1, oacc[nt][1] * inv1, hi, lo);
        size_t off = ((size_t)(b * SS + r1)) * EE + h * DD + d;
        *(unsigned*)&g_oh[off] = hi;
        *(unsigned*)&g_ol[off] = lo;
        split_pair_h(oacc[nt][2] * inv2, oacc[nt][3] * inv2, hi, lo);
        off = ((size_t)(b * SS + r1 + 8)) * EE + h * DD + d;
        *(unsigned*)&g_oh[off] = hi;
        *(unsigned*)&g_ol[off] = lo;
    }
}

// ---------------------------------------------------------------------------
extern "C" void kernel_launch(void* const* d_in, const int* in_sizes, int n_in,
                              void* d_out, int out_size) {
    const float* x = (const float*)d_in[0];      // (B, S, E)
    const float* w_qkv = (const float*)d_in[1];  // (E, 3E)
    const float* w_out = (const float*)d_in[2];  // (E, E)
    float* out = (float*)d_out;                  // (B, S, E)

    __half *p_xh, *p_xl, *p_wqh, *p_wql, *p_woh, *p_wol, *p_oh, *p_ol;
    cudaGetSymbolAddress((void**)&p_xh, g_xh);
    cudaGetSymbolAddress((void**)&p_xl, g_xl);
    cudaGetSymbolAddress((void**)&p_wqh, g_wqh);
    cudaGetSymbolAddress((void**)&p_wql, g_wql);
    cudaGetSymbolAddress((void**)&p_woh, g_woh);
    cudaGetSymbolAddress((void**)&p_wol, g_wol);
    cudaGetSymbolAddress((void**)&p_oh, g_oh);
    cudaGetSymbolAddress((void**)&p_ol, g_ol);

    // 0) split inputs once (weights' lo planes are written but unused)
    split_kernel<<<(BB*SS*EE/4 + 255) / 256, 256>>>(x, p_xh, p_xl, BB*SS*EE/4);
    split_kernel<<<(EE*NQKV/4 + 255) / 256, 256>>>(w_qkv, p_wqh, p_wql, EE*NQKV/4);
    split_kernel<<<(EE*EE/4 + 255) / 256, 256>>>(w_out, p_woh, p_wol, EE*EE/4);

    // 1) QKV projection, scatter Q/K/V hi/lo (Q pre-scaled)
    cudaFuncSetAttribute(mma_gemm3<NQKV, true>,
                         cudaFuncAttributeMaxDynamicSharedMemorySize, G3_SMEM);
    mma_gemm3<NQKV, true><<<dim3(NQKV / 128, (BB * SS) / 128), 256, G3_SMEM>>>(
        p_xh, p_xl, p_wqh, nullptr);

    // 2) Flash attention
    const int attn_smem = (AT_KV + 4 * AT_T) * (int)sizeof(__half);
    cudaFuncSetAttribute(attn_mma2, cudaFuncAttributeMaxDynamicSharedMemorySize,
                         attn_smem);
    attn_mma2<<<dim3(SS / 128, HH, BB), 256, attn_smem>>>();

    // 3) Output projection
    cudaFuncSetAttribute(mma_gemm3<EE, false>,
                         cudaFuncAttributeMaxDynamicSharedMemorySize, G3_SMEM);
    mma_gemm3<EE, false><<<dim3(EE / 128, (BB * SS) / 128), 256, G3_SMEM>>>(
        p_oh, p_ol, p_woh, out);
}

// round 10
// speedup vs baseline: 2.2260x; 1.5874x over previous
#include <cuda_runtime.h>
#include <cuda_fp16.h>
#include <cstdint>
#include <math.h>

#define BB 2
#define SS 2048
#define EE 1024
#define HH 16
#define DD 64
#define NQKV 3072

// ---------------------------------------------------------------------------
// Scratch (device globals — allocation-free). Plain fp16 everywhere.
// ---------------------------------------------------------------------------
__device__ __half g_x16[BB*SS*EE];       // x
__device__ __half g_wq16[EE*NQKV];       // w_qkv
__device__ __half g_wo16[EE*EE];         // w_out
__device__ __half g_q16[BB*HH*SS*DD];    // Q (pre-scaled by 1/8)
__device__ __half g_k16[BB*HH*SS*DD];
__device__ __half g_v16[BB*HH*SS*DD];
__device__ __half g_o16[BB*SS*EE];       // attention output

// single TU-wide dynamic smem symbol (char) — cast per kernel
extern __shared__ __align__(16) char dynsmem[];

// ---------------------------------------------------------------------------
// PTX wrappers
// ---------------------------------------------------------------------------
__device__ __forceinline__ void ldsm4(unsigned r[4], uint32_t a) {
    asm volatile("ldmatrix.sync.aligned.m8n8.x4.shared.b16 {%0,%1,%2,%3}, [%4];\n"
                 : "=r"(r[0]), "=r"(r[1]), "=r"(r[2]), "=r"(r[3]) : "r"(a));
}
__device__ __forceinline__ void ldsm4t(unsigned r[4], uint32_t a) {
    asm volatile("ldmatrix.sync.aligned.m8n8.x4.trans.shared.b16 {%0,%1,%2,%3}, [%4];\n"
                 : "=r"(r[0]), "=r"(r[1]), "=r"(r[2]), "=r"(r[3]) : "r"(a));
}
__device__ __forceinline__ void mma_f16(float c[4], const unsigned a[4], const unsigned b[2]) {
    asm volatile(
        "mma.sync.aligned.m16n8k16.row.col.f32.f16.f16.f32 "
        "{%0,%1,%2,%3}, {%4,%5,%6,%7}, {%8,%9}, {%0,%1,%2,%3};\n"
        : "+f"(c[0]), "+f"(c[1]), "+f"(c[2]), "+f"(c[3])
        : "r"(a[0]), "r"(a[1]), "r"(a[2]), "r"(a[3]), "r"(b[0]), "r"(b[1]));
}
__device__ __forceinline__ void cp16(uint32_t s, const void* g) {
    asm volatile("cp.async.cg.shared.global [%0], [%1], 16;\n" :: "r"(s), "l"(g));
}
__device__ __forceinline__ void cp_commit() {
    asm volatile("cp.async.commit_group;\n" ::: "memory");
}
template <int N>
__device__ __forceinline__ void cp_wait() {
    asm volatile("cp.async.wait_group %0;\n" :: "n"(N) : "memory");
}
__device__ __forceinline__ unsigned pack_h2(float x, float y) {
    __half2 h2 = __floats2half2_rn(x, y);
    return *reinterpret_cast<unsigned*>(&h2);
}
__device__ __forceinline__ uint32_t smem_u32(const void* p) {
    return (uint32_t)__cvta_generic_to_shared(p);
}

// ---------------------------------------------------------------------------
// Elementwise fp32 -> fp16 convert
// ---------------------------------------------------------------------------
__global__ __launch_bounds__(256) void conv_kernel(const float* __restrict__ src,
                                                   __half* __restrict__ dst,
                                                   int n4) {
    int i = blockIdx.x * 256 + threadIdx.x;
    if (i < n4) {
        float4 v = *(const float4*)(src + (size_t)i * 4);
        *(uint2*)(dst + (size_t)i * 4) =
            make_uint2(pack_h2(v.x, v.y), pack_h2(v.z, v.w));
    }
}

// ---------------------------------------------------------------------------
// fp16 GEMM: C[M, NC] = A[M,1024] @ W[1024,NC]
// BM=128, BN=128, BK=32, 8 warps, warp tile 32x64, 2 CTAs/SM.
// 3-stage cp.async ring, one sync per k-tile.
// Stage layout (elems): [A 128*40 | B 32*136]
// ---------------------------------------------------------------------------
#define ST_A 5120                          // 128*40 elems
#define ST_B 4352                          // 32*136 elems
#define ST_BYTES ((ST_A + ST_B) * 2)       // 18944 B
#define G3_SMEM (3 * ST_BYTES)             // 56832 B

template <int NC, bool SCATTER>
__global__ __launch_bounds__(256, 2) void mma_gemm4(const __half* __restrict__ A_g,
                                                    const __half* __restrict__ B_g,
                                                    float* __restrict__ C) {
    char* smem = dynsmem;
    const int tid = threadIdx.x;
    const int lane = tid & 31, wid = tid >> 5;
    const int wm = (wid & 3) * 32, wn = (wid >> 2) * 64;
    const int m0 = blockIdx.y * 128, n0 = blockIdx.x * 128;

    const uint32_t uS = smem_u32(smem);
    const int lm_r = lane & 15, lm_c = (lane >> 4) * 8;
    const uint32_t aoff0 = ((wm + lm_r) * 40 + lm_c) * 2;
    const uint32_t boff0 = (lm_r * 136 + wn + lm_c) * 2;

    float acc[2][8][4];
#pragma unroll
    for (int i = 0; i < 2; i++)
#pragma unroll
        for (int j = 0; j < 8; j++)
#pragma unroll
            for (int q = 0; q < 4; q++) acc[i][j][q] = 0.0f;

    auto load_tile = [&](int slot, int k0) {
        uint32_t base = uS + slot * ST_BYTES;
#pragma unroll
        for (int i = 0; i < 2; i++) {
            int idx = tid + i * 256;              // 0..511
            int r = idx >> 2, c8 = (idx & 3) * 8; // r 0..127, c8 0..24
            cp16(base + (r * 40 + c8) * 2,
                 A_g + (size_t)(m0 + r) * EE + k0 + c8);
        }
        uint32_t bbase = base + ST_A * 2;
#pragma unroll
        for (int i = 0; i < 2; i++) {
            int idx = tid + i * 256;
            int r = idx >> 4, c8 = (idx & 15) * 8; // r 0..31, c8 0..120
            cp16(bbase + (r * 136 + c8) * 2,
                 B_g + (size_t)(k0 + r) * NC + n0 + c8);
        }
    };

    load_tile(0, 0);  cp_commit();
    load_tile(1, 32); cp_commit();

#pragma unroll 1
    for (int kt = 0; kt < 32; kt++) {
        const int slot = kt - (kt / 3) * 3;
        if (kt < 31) cp_wait<1>(); else cp_wait<0>();
        __syncthreads();

        if (kt + 2 < 32) {
            int ns = (kt + 2) - ((kt + 2) / 3) * 3;
            load_tile(ns, (kt + 2) * 32);
            cp_commit();
        }

        const uint32_t uA = uS + slot * ST_BYTES;
        const uint32_t uB = uA + ST_A * 2;

#pragma unroll
        for (int ks = 0; ks < 2; ks++) {
            const int kk = ks * 16;
            unsigned ah[2][4];
#pragma unroll
            for (int tm = 0; tm < 2; tm++) {
                uint32_t off = aoff0 + (tm * 16 * 40 + kk) * 2;
                ldsm4(ah[tm], uA + off);
            }
#pragma unroll
            for (int g = 0; g < 4; g++) {
                unsigned bh[4];
                uint32_t off = boff0 + (kk * 136 + g * 16) * 2;
                ldsm4t(bh, uB + off);
                // 4 independent accumulators
                mma_f16(acc[0][2 * g],     ah[0], &bh[0]);
                mma_f16(acc[0][2 * g + 1], ah[0], &bh[2]);
                mma_f16(acc[1][2 * g],     ah[1], &bh[0]);
                mma_f16(acc[1][2 * g + 1], ah[1], &bh[2]);
            }
        }
    }

    if (SCATTER) {
#pragma unroll
        for (int tm = 0; tm < 2; tm++)
#pragma unroll
            for (int nt = 0; nt < 8; nt++) {
                int f = n0 + wn + nt * 8 + (lane & 3) * 2;
                int cid = f >> 10;
                int hh = (f >> 6) & (HH - 1);
                int d = f & (DD - 1);
                float sc = (cid == 0) ? 0.125f : 1.0f;
                __half* dst = (cid == 0) ? g_q16 : (cid == 1) ? g_k16 : g_v16;
#pragma unroll
                for (int half = 0; half < 2; half++) {
                    int row = m0 + wm + tm * 16 + (lane >> 2) + half * 8;
                    int b = row >> 11, s = row & (SS - 1);
                    size_t off = ((size_t)((b * HH + hh) * SS + s)) * DD + d;
                    *(unsigned*)&dst[off] = pack_h2(acc[tm][nt][half * 2] * sc,
                                                    acc[tm][nt][half * 2 + 1] * sc);
                }
            }
    } else {
#pragma unroll
        for (int tm = 0; tm < 2; tm++)
#pragma unroll
            for (int nt = 0; nt < 8; nt++) {
                int col = n0 + wn + nt * 8 + (lane & 3) * 2;
#pragma unroll
                for (int half = 0; half < 2; half++) {
                    int row = m0 + wm + tm * 16 + (lane >> 2) + half * 8;
                    float2 v = make_float2(acc[tm][nt][half * 2],
                                           acc[tm][nt][half * 2 + 1]);
                    *(float2*)&C[(size_t)row * NC + col] = v;
                }
            }
    }
}

// ---------------------------------------------------------------------------
// Flash attention, plain fp16 mma. CTA = (b, h, 128 q rows), 8 warps,
// kv tiles of 64, double-buffered, 2 CTAs/SM.
// smem elems: Q[128*72] + 2 bufs x (K[64*72] + V[64*72])
// ---------------------------------------------------------------------------
#define AT_Q 9216            // 128*72 elems
#define AT_T 4608            // 64*72 elems

__global__ __launch_bounds__(256, 2) void attn_mma3() {
    __half* smem = (__half*)dynsmem;
    const int tid = threadIdx.x, lane = tid & 31, w = tid >> 5;
    const int q0 = blockIdx.x * 128, h = blockIdx.y, b = blockIdx.z;
    const size_t hb = (size_t)(b * HH + h) * SS * DD;

    const uint32_t uS = smem_u32(smem);
    const uint32_t uQ = uS;

    const int lm_r = lane & 15, lm_c = (lane >> 4) * 8;
    const int bn_r = (lane & 7) + (lane >> 4) * 8;
    const int bn_c = ((lane >> 3) & 1) * 8;

    // buf layout after Q: [K | V] per buffer
    auto kv_base = [&](int buf, int t) -> uint32_t {
        return uS + (AT_Q + (buf * 2 + t) * AT_T) * 2;
    };

    auto load_kv = [&](int buf, int kv) {
        const __half* s0 = g_k16 + hb + (size_t)kv * DD;
        const __half* s1 = g_v16 + hb + (size_t)kv * DD;
#pragma unroll
        for (int i = 0; i < 2; i++) {
            int idx = tid + i * 256;
            int r = idx >> 3, c8 = (idx & 7) * 8;
            uint32_t so = (r * 72 + c8) * 2;
            int go = r * DD + c8;
            cp16(kv_base(buf, 0) + so, s0 + go);
            cp16(kv_base(buf, 1) + so, s1 + go);
        }
    };

#pragma unroll
    for (int i = 0; i < 4; i++) {
        int idx = tid + i * 256;
        int r = idx >> 3, c8 = (idx & 7) * 8;
        uint32_t so = (r * 72 + c8) * 2;
        size_t go = hb + (size_t)(q0 + r) * DD + c8;
        cp16(uQ + so, g_q16 + go);
    }
    load_kv(0, 0);
    cp_commit();

    float m1 = -1.0e30f, m2 = -1.0e30f, l1 = 0.0f, l2 = 0.0f;
    float oacc[8][4];
#pragma unroll
    for (int j = 0; j < 8; j++)
#pragma unroll
        for (int q = 0; q < 4; q++) oacc[j][q] = 0.0f;

#pragma unroll 1
    for (int ti = 0; ti < 32; ti++) {
        const int buf = ti & 1;
        if (ti + 1 < 32) load_kv(buf ^ 1, (ti + 1) * 64);
        cp_commit();
        if (ti + 1 < 32) cp_wait<1>(); else cp_wait<0>();
        __syncthreads();

        const uint32_t uK = kv_base(buf, 0);
        const uint32_t uV = kv_base(buf, 1);

        // S = Q @ K^T (scale folded into Q)
        float sacc[8][4];
#pragma unroll
        for (int j = 0; j < 8; j++)
#pragma unroll
            for (int q = 0; q < 4; q++) sacc[j][q] = 0.0f;

#pragma unroll
        for (int kt = 0; kt < 4; kt++) {
            unsigned aq[4];
            uint32_t qoff = ((w * 16 + lm_r) * 72 + kt * 16 + lm_c) * 2;
            ldsm4(aq, uQ + qoff);
#pragma unroll
            for (int g = 0; g < 4; g++) {
                unsigned bh[4];
                uint32_t koff = ((g * 16 + bn_r) * 72 + kt * 16 + bn_c) * 2;
                ldsm4(bh, uK + koff);
                mma_f16(sacc[2 * g],     aq, &bh[0]);
                mma_f16(sacc[2 * g + 1], aq, &bh[2]);
            }
        }

        // Online softmax
        float mx1 = -1.0e30f, mx2 = -1.0e30f;
#pragma unroll
        for (int nt = 0; nt < 8; nt++) {
            mx1 = fmaxf(mx1, fmaxf(sacc[nt][0], sacc[nt][1]));
            mx2 = fmaxf(mx2, fmaxf(sacc[nt][2], sacc[nt][3]));
        }
#pragma unroll
        for (int off = 1; off <= 2; off <<= 1) {
            mx1 = fmaxf(mx1, __shfl_xor_sync(0xffffffffu, mx1, off));
            mx2 = fmaxf(mx2, __shfl_xor_sync(0xffffffffu, mx2, off));
        }
        float mn1 = fmaxf(m1, mx1), mn2 = fmaxf(m2, mx2);
        float fac1 = __expf(m1 - mn1), fac2 = __expf(m2 - mn2);
        float rs1 = 0.0f, rs2 = 0.0f;
#pragma unroll
        for (int nt = 0; nt < 8; nt++) {
            sacc[nt][0] = __expf(sacc[nt][0] - mn1);
            sacc[nt][1] = __expf(sacc[nt][1] - mn1);
            sacc[nt][2] = __expf(sacc[nt][2] - mn2);
            sacc[nt][3] = __expf(sacc[nt][3] - mn2);
            rs1 += sacc[nt][0] + sacc[nt][1];
            rs2 += sacc[nt][2] + sacc[nt][3];
        }
#pragma unroll
        for (int off = 1; off <= 2; off <<= 1) {
            rs1 += __shfl_xor_sync(0xffffffffu, rs1, off);
            rs2 += __shfl_xor_sync(0xffffffffu, rs2, off);
        }
        l1 = l1 * fac1 + rs1;
        l2 = l2 * fac2 + rs2;
        m1 = mn1;
        m2 = mn2;
#pragma unroll
        for (int nt = 0; nt < 8; nt++) {
            oacc[nt][0] *= fac1;
            oacc[nt][1] *= fac1;
            oacc[nt][2] *= fac2;
            oacc[nt][3] *= fac2;
        }

        // P fragments (single fp16) straight from sacc registers
        unsigned ph[4][4];
#pragma unroll
        for (int kt = 0; kt < 4; kt++) {
            ph[kt][0] = pack_h2(sacc[2 * kt][0],     sacc[2 * kt][1]);
            ph[kt][1] = pack_h2(sacc[2 * kt][2],     sacc[2 * kt][3]);
            ph[kt][2] = pack_h2(sacc[2 * kt + 1][0], sacc[2 * kt + 1][1]);
            ph[kt][3] = pack_h2(sacc[2 * kt + 1][2], sacc[2 * kt + 1][3]);
        }

        // O += P @ V
#pragma unroll
        for (int kt = 0; kt < 4; kt++) {
#pragma unroll
            for (int dg = 0; dg < 4; dg++) {
                unsigned vh[4];
                uint32_t voff = ((kt * 16 + lm_r) * 72 + dg * 16 + lm_c) * 2;
                ldsm4t(vh, uV + voff);
                mma_f16(oacc[2 * dg],     ph[kt], &vh[0]);
                mma_f16(oacc[2 * dg + 1], ph[kt], &vh[2]);
            }
        }
        __syncthreads();
    }

    // normalize + store O (single fp16)
    float inv1 = 1.0f / l1, inv2 = 1.0f / l2;
    int r1 = q0 + w * 16 + (lane >> 2);
#pragma unroll
    for (int nt = 0; nt < 8; nt++) {
        int d = nt * 8 + (lane & 3) * 2;
        size_t off = ((size_t)(b * SS + r1)) * EE + h * DD + d;
        *(unsigned*)&g_o16[off] = pack_h2(oacc[nt][0] * inv1, oacc[nt][1] * inv1);
        off = ((size_t)(b * SS + r1 + 8)) * EE + h * DD + d;
        *(unsigned*)&g_o16[off] = pack_h2(oacc[nt][2] * inv2, oacc[nt][3] * inv2);
    }
}

// ---------------------------------------------------------------------------
extern "C" void kernel_launch(void* const* d_in, const int* in_sizes, int n_in,
                              void* d_out, int out_size) {
    const float* x = (const float*)d_in[0];      // (B, S, E)
    const float* w_qkv = (const float*)d_in[1];  // (E, 3E)
    const float* w_out = (const float*)d_in[2];  // (E, E)
    float* out = (float*)d_out;                  // (B, S, E)

    __half *p_x, *p_wq, *p_wo, *p_o;
    cudaGetSymbolAddress((void**)&p_x, g_x16);
    cudaGetSymbolAddress((void**)&p_wq, g_wq16);
    cudaGetSymbolAddress((void**)&p_wo, g_wo16);
    cudaGetSymbolAddress((void**)&p_o, g_o16);

    // 0) convert inputs once
    conv_kernel<<<(BB*SS*EE/4 + 255) / 256, 256>>>(x, p_x, BB*SS*EE/4);
    conv_kernel<<<(EE*NQKV/4 + 255) / 256, 256>>>(w_qkv, p_wq, EE*NQKV/4);
    conv_kernel<<<(EE*EE/4 + 255) / 256, 256>>>(w_out, p_wo, EE*EE/4);

    // 1) QKV projection, scatter Q/K/V (Q pre-scaled)
    cudaFuncSetAttribute(mma_gemm4<NQKV, true>,
                         cudaFuncAttributeMaxDynamicSharedMemorySize, G3_SMEM);
    mma_gemm4<NQKV, true><<<dim3(NQKV / 128, (BB * SS) / 128), 256, G3_SMEM>>>(
        p_x, p_wq, nullptr);

    // 2) Flash attention
    const int attn_smem = (AT_Q + 4 * AT_T) * (int)sizeof(__half);
    cudaFuncSetAttribute(attn_mma3, cudaFuncAttributeMaxDynamicSharedMemorySize,
                         attn_smem);
    attn_mma3<<<dim3(SS / 128, HH, BB), 256, attn_smem>>>();

    // 3) Output projection
    cudaFuncSetAttribute(mma_gemm4<EE, false>,
                         cudaFuncAttributeMaxDynamicSharedMemorySize, G3_SMEM);
    mma_gemm4<EE, false><<<dim3(EE / 128, (BB * SS) / 128), 256, G3_SMEM>>>(
        p_o, p_wo, out);
}

// round 11
// speedup vs baseline: 2.3374x; 1.0501x over previous
#include <cuda_runtime.h>
#include <cuda_fp16.h>
#include <cstdint>
#include <math.h>

#define BB 2
#define SS 2048
#define EE 1024
#define HH 16
#define DD 64
#define NQKV 3072

// ---------------------------------------------------------------------------
// Scratch (device globals — allocation-free). Plain fp16 everywhere.
// ---------------------------------------------------------------------------
__device__ __half g_x16[BB*SS*EE];       // x
__device__ __half g_wq16[EE*NQKV];       // w_qkv
__device__ __half g_wo16[EE*EE];         // w_out
__device__ __half g_q16[BB*HH*SS*DD];    // Q (pre-scaled by 0.125*log2e)
__device__ __half g_k16[BB*HH*SS*DD];
__device__ __half g_v16[BB*HH*SS*DD];
__device__ __half g_o16[BB*SS*EE];       // attention output

// single TU-wide dynamic smem symbol (char) — cast per kernel
extern __shared__ __align__(16) char dynsmem[];

// ---------------------------------------------------------------------------
// PTX wrappers
// ---------------------------------------------------------------------------
__device__ __forceinline__ void ldsm4(unsigned r[4], uint32_t a) {
    asm volatile("ldmatrix.sync.aligned.m8n8.x4.shared.b16 {%0,%1,%2,%3}, [%4];\n"
                 : "=r"(r[0]), "=r"(r[1]), "=r"(r[2]), "=r"(r[3]) : "r"(a));
}
__device__ __forceinline__ void ldsm4t(unsigned r[4], uint32_t a) {
    asm volatile("ldmatrix.sync.aligned.m8n8.x4.trans.shared.b16 {%0,%1,%2,%3}, [%4];\n"
                 : "=r"(r[0]), "=r"(r[1]), "=r"(r[2]), "=r"(r[3]) : "r"(a));
}
__device__ __forceinline__ void mma_f16(float c[4], const unsigned a[4], const unsigned b[2]) {
    asm volatile(
        "mma.sync.aligned.m16n8k16.row.col.f32.f16.f16.f32 "
        "{%0,%1,%2,%3}, {%4,%5,%6,%7}, {%8,%9}, {%0,%1,%2,%3};\n"
        : "+f"(c[0]), "+f"(c[1]), "+f"(c[2]), "+f"(c[3])
        : "r"(a[0]), "r"(a[1]), "r"(a[2]), "r"(a[3]), "r"(b[0]), "r"(b[1]));
}
__device__ __forceinline__ void cp16(uint32_t s, const void* g) {
    asm volatile("cp.async.cg.shared.global [%0], [%1], 16;\n" :: "r"(s), "l"(g));
}
__device__ __forceinline__ void cp_commit() {
    asm volatile("cp.async.commit_group;\n" ::: "memory");
}
template <int N>
__device__ __forceinline__ void cp_wait() {
    asm volatile("cp.async.wait_group %0;\n" :: "n"(N) : "memory");
}
__device__ __forceinline__ unsigned pack_h2(float x, float y) {
    __half2 h2 = __floats2half2_rn(x, y);
    return *reinterpret_cast<unsigned*>(&h2);
}
// packed fp16 2^x (single MUFU instruction for two values)
__device__ __forceinline__ unsigned h2_ex2(unsigned in) {
    unsigned out;
    asm("ex2.approx.f16x2 %0, %1;" : "=r"(out) : "r"(in));
    return out;
}
__device__ __forceinline__ uint32_t smem_u32(const void* p) {
    return (uint32_t)__cvta_generic_to_shared(p);
}

// ---------------------------------------------------------------------------
// Elementwise fp32 -> fp16 convert
// ---------------------------------------------------------------------------
__global__ __launch_bounds__(256) void conv_kernel(const float* __restrict__ src,
                                                   __half* __restrict__ dst,
                                                   int n4) {
    int i = blockIdx.x * 256 + threadIdx.x;
    if (i < n4) {
        float4 v = *(const float4*)(src + (size_t)i * 4);
        *(uint2*)(dst + (size_t)i * 4) =
            make_uint2(pack_h2(v.x, v.y), pack_h2(v.z, v.w));
    }
}

// ---------------------------------------------------------------------------
// fp16 GEMM: C[M, NC] = A[M,1024] @ W[1024,NC]
// BM=128, BN=128, BK=32, 8 warps, warp tile 32x64, 2 CTAs/SM.
// 4-stage cp.async ring (power-of-2 slots), depth-3 prefetch, 1 sync/k-tile.
// Stage layout (elems): [A 128*40 | B 32*136]
// ---------------------------------------------------------------------------
#define ST_A 5120                          // 128*40 elems
#define ST_B 4352                          // 32*136 elems
#define ST_BYTES ((ST_A + ST_B) * 2)       // 18944 B
#define G4_SMEM (4 * ST_BYTES)             // 75776 B

template <int NC, bool SCATTER>
__global__ __launch_bounds__(256, 2) void mma_gemm4(const __half* __restrict__ A_g,
                                                    const __half* __restrict__ B_g,
                                                    float* __restrict__ C) {
    char* smem = dynsmem;
    const int tid = threadIdx.x;
    const int lane = tid & 31, wid = tid >> 5;
    const int wm = (wid & 3) * 32, wn = (wid >> 2) * 64;
    const int m0 = blockIdx.y * 128, n0 = blockIdx.x * 128;

    const uint32_t uS = smem_u32(smem);
    const int lm_r = lane & 15, lm_c = (lane >> 4) * 8;
    const uint32_t aoff0 = ((wm + lm_r) * 40 + lm_c) * 2;
    const uint32_t boff0 = (lm_r * 136 + wn + lm_c) * 2;

    float acc[2][8][4];
#pragma unroll
    for (int i = 0; i < 2; i++)
#pragma unroll
        for (int j = 0; j < 8; j++)
#pragma unroll
            for (int q = 0; q < 4; q++) acc[i][j][q] = 0.0f;

    auto load_tile = [&](int slot, int k0) {
        uint32_t base = uS + slot * ST_BYTES;
#pragma unroll
        for (int i = 0; i < 2; i++) {
            int idx = tid + i * 256;              // 0..511
            int r = idx >> 2, c8 = (idx & 3) * 8; // r 0..127, c8 0..24
            cp16(base + (r * 40 + c8) * 2,
                 A_g + (size_t)(m0 + r) * EE + k0 + c8);
        }
        uint32_t bbase = base + ST_A * 2;
#pragma unroll
        for (int i = 0; i < 2; i++) {
            int idx = tid + i * 256;
            int r = idx >> 4, c8 = (idx & 15) * 8; // r 0..31, c8 0..120
            cp16(bbase + (r * 136 + c8) * 2,
                 B_g + (size_t)(k0 + r) * NC + n0 + c8);
        }
    };

    load_tile(0, 0);  cp_commit();
    load_tile(1, 32); cp_commit();
    load_tile(2, 64); cp_commit();

#pragma unroll 1
    for (int kt = 0; kt < 32; kt++) {
        const int slot = kt & 3;
        if (kt < 30) cp_wait<2>();
        else if (kt == 30) cp_wait<1>();
        else cp_wait<0>();
        __syncthreads();

        if (kt + 3 < 32) {
            load_tile((kt + 3) & 3, (kt + 3) * 32);
            cp_commit();
        }

        const uint32_t uA = uS + slot * ST_BYTES;
        const uint32_t uB = uA + ST_A * 2;

#pragma unroll
        for (int ks = 0; ks < 2; ks++) {
            const int kk = ks * 16;
            unsigned ah[2][4];
#pragma unroll
            for (int tm = 0; tm < 2; tm++) {
                uint32_t off = aoff0 + (tm * 16 * 40 + kk) * 2;
                ldsm4(ah[tm], uA + off);
            }
#pragma unroll
            for (int g = 0; g < 4; g++) {
                unsigned bh[4];
                uint32_t off = boff0 + (kk * 136 + g * 16) * 2;
                ldsm4t(bh, uB + off);
                mma_f16(acc[0][2 * g],     ah[0], &bh[0]);
                mma_f16(acc[0][2 * g + 1], ah[0], &bh[2]);
                mma_f16(acc[1][2 * g],     ah[1], &bh[0]);
                mma_f16(acc[1][2 * g + 1], ah[1], &bh[2]);
            }
        }
    }

    if (SCATTER) {
        const float LOG2E_SC = 0.125f * 1.44269504088896340736f;
#pragma unroll
        for (int tm = 0; tm < 2; tm++)
#pragma unroll
            for (int nt = 0; nt < 8; nt++) {
                int f = n0 + wn + nt * 8 + (lane & 3) * 2;
                int cid = f >> 10;
                int hh = (f >> 6) & (HH - 1);
                int d = f & (DD - 1);
                float sc = (cid == 0) ? LOG2E_SC : 1.0f;   // Q scaled for log2-domain softmax
                __half* dst = (cid == 0) ? g_q16 : (cid == 1) ? g_k16 : g_v16;
#pragma unroll
                for (int half = 0; half < 2; half++) {
                    int row = m0 + wm + tm * 16 + (lane >> 2) + half * 8;
                    int b = row >> 11, s = row & (SS - 1);
                    size_t off = ((size_t)((b * HH + hh) * SS + s)) * DD + d;
                    *(unsigned*)&dst[off] = pack_h2(acc[tm][nt][half * 2] * sc,
                                                    acc[tm][nt][half * 2 + 1] * sc);
                }
            }
    } else {
#pragma unroll
        for (int tm = 0; tm < 2; tm++)
#pragma unroll
            for (int nt = 0; nt < 8; nt++) {
                int col = n0 + wn + nt * 8 + (lane & 3) * 2;
#pragma unroll
                for (int half = 0; half < 2; half++) {
                    int row = m0 + wm + tm * 16 + (lane >> 2) + half * 8;
                    float2 v = make_float2(acc[tm][nt][half * 2],
                                           acc[tm][nt][half * 2 + 1]);
                    *(float2*)&C[(size_t)row * NC + col] = v;
                }
            }
    }
}

// ---------------------------------------------------------------------------
// Flash attention, fp16 mma, log2-domain softmax with fp16 ex2.
// CTA = (b, h, 128 q rows), 8 warps, kv tiles of 64, double-buffered,
// 2 CTAs/SM. Row sums via MMA against a constant ones B-fragment.
// smem elems: Q[128*72] + 2 bufs x (K[64*72] + V[64*72])
// ---------------------------------------------------------------------------
#define AT_Q 9216            // 128*72 elems
#define AT_T 4608            // 64*72 elems

__global__ __launch_bounds__(256, 2) void attn_mma4() {
    __half* smem = (__half*)dynsmem;
    const int tid = threadIdx.x, lane = tid & 31, w = tid >> 5;
    const int q0 = blockIdx.x * 128, h = blockIdx.y, b = blockIdx.z;
    const size_t hb = (size_t)(b * HH + h) * SS * DD;

    const uint32_t uS = smem_u32(smem);
    const uint32_t uQ = uS;

    const int lm_r = lane & 15, lm_c = (lane >> 4) * 8;
    const int bn_r = (lane & 7) + (lane >> 4) * 8;
    const int bn_c = ((lane >> 3) & 1) * 8;

    // Constant B fragment for row-sum MMA: B[k][0] = 1 for all k, else 0.
    // m16n8k16 B-frag: lanes 0-3 hold n=0 -> half2(1,1) in both regs.
    unsigned bones[2];
    bones[0] = bones[1] = (lane < 4) ? 0x3C003C00u : 0u;

    auto kv_base = [&](int buf, int t) -> uint32_t {
        return uS + (AT_Q + (buf * 2 + t) * AT_T) * 2;
    };

    auto load_kv = [&](int buf, int kv) {
        const __half* s0 = g_k16 + hb + (size_t)kv * DD;
        const __half* s1 = g_v16 + hb + (size_t)kv * DD;
#pragma unroll
        for (int i = 0; i < 2; i++) {
            int idx = tid + i * 256;
            int r = idx >> 3, c8 = (idx & 7) * 8;
            uint32_t so = (r * 72 + c8) * 2;
            int go = r * DD + c8;
            cp16(kv_base(buf, 0) + so, s0 + go);
            cp16(kv_base(buf, 1) + so, s1 + go);
        }
    };

#pragma unroll
    for (int i = 0; i < 4; i++) {
        int idx = tid + i * 256;
        int r = idx >> 3, c8 = (idx & 7) * 8;
        uint32_t so = (r * 72 + c8) * 2;
        size_t go = hb + (size_t)(q0 + r) * DD + c8;
        cp16(uQ + so, g_q16 + go);
    }
    load_kv(0, 0);
    cp_commit();

    // m in log2 domain
    float m1 = -1.0e30f, m2 = -1.0e30f, l1 = 0.0f, l2 = 0.0f;
    float oacc[8][4];
#pragma unroll
    for (int j = 0; j < 8; j++)
#pragma unroll
        for (int q = 0; q < 4; q++) oacc[j][q] = 0.0f;

#pragma unroll 1
    for (int ti = 0; ti < 32; ti++) {
        const int buf = ti & 1;
        if (ti + 1 < 32) load_kv(buf ^ 1, (ti + 1) * 64);
        cp_commit();
        if (ti + 1 < 32) cp_wait<1>(); else cp_wait<0>();
        __syncthreads();

        const uint32_t uK = kv_base(buf, 0);
        const uint32_t uV = kv_base(buf, 1);

        // S = Q @ K^T  (log2e * scale folded into Q)
        float sacc[8][4];
#pragma unroll
        for (int j = 0; j < 8; j++)
#pragma unroll
            for (int q = 0; q < 4; q++) sacc[j][q] = 0.0f;

#pragma unroll
        for (int kt = 0; kt < 4; kt++) {
            unsigned aq[4];
            uint32_t qoff = ((w * 16 + lm_r) * 72 + kt * 16 + lm_c) * 2;
            ldsm4(aq, uQ + qoff);
#pragma unroll
            for (int g = 0; g < 4; g++) {
                unsigned bh[4];
                uint32_t koff = ((g * 16 + bn_r) * 72 + kt * 16 + bn_c) * 2;
                ldsm4(bh, uK + koff);
                mma_f16(sacc[2 * g],     aq, &bh[0]);
                mma_f16(sacc[2 * g + 1], aq, &bh[2]);
            }
        }

        // Row max (log2 domain)
        float mx1 = -1.0e30f, mx2 = -1.0e30f;
#pragma unroll
        for (int nt = 0; nt < 8; nt++) {
            mx1 = fmaxf(mx1, fmaxf(sacc[nt][0], sacc[nt][1]));
            mx2 = fmaxf(mx2, fmaxf(sacc[nt][2], sacc[nt][3]));
        }
#pragma unroll
        for (int off = 1; off <= 2; off <<= 1) {
            mx1 = fmaxf(mx1, __shfl_xor_sync(0xffffffffu, mx1, off));
            mx2 = fmaxf(mx2, __shfl_xor_sync(0xffffffffu, mx2, off));
        }
        float mn1 = fmaxf(m1, mx1), mn2 = fmaxf(m2, mx2);
        float fac1 = exp2f(m1 - mn1), fac2 = exp2f(m2 - mn2);
        m1 = mn1;
        m2 = mn2;

        // P = 2^(S - mn) in packed fp16 via ex2.approx.f16x2
        unsigned ph[4][4];
#pragma unroll
        for (int kt = 0; kt < 4; kt++) {
            ph[kt][0] = h2_ex2(pack_h2(sacc[2 * kt][0] - mn1,     sacc[2 * kt][1] - mn1));
            ph[kt][1] = h2_ex2(pack_h2(sacc[2 * kt][2] - mn2,     sacc[2 * kt][3] - mn2));
            ph[kt][2] = h2_ex2(pack_h2(sacc[2 * kt + 1][0] - mn1, sacc[2 * kt + 1][1] - mn1));
            ph[kt][3] = h2_ex2(pack_h2(sacc[2 * kt + 1][2] - mn2, sacc[2 * kt + 1][3] - mn2));
        }

        // Row sums via MMA with constant ones-fragment (exactly consistent
        // with the fp16 P used in P@V below).
        float racc[4] = {0.0f, 0.0f, 0.0f, 0.0f};
#pragma unroll
        for (int kt = 0; kt < 4; kt++) mma_f16(racc, ph[kt], bones);
        float rs1 = __shfl_sync(0xffffffffu, racc[0], 0, 4);
        float rs2 = __shfl_sync(0xffffffffu, racc[2], 0, 4);

        l1 = l1 * fac1 + rs1;
        l2 = l2 * fac2 + rs2;
#pragma unroll
        for (int nt = 0; nt < 8; nt++) {
            oacc[nt][0] *= fac1;
            oacc[nt][1] *= fac1;
            oacc[nt][2] *= fac2;
            oacc[nt][3] *= fac2;
        }

        // O += P @ V
#pragma unroll
        for (int kt = 0; kt < 4; kt++) {
#pragma unroll
            for (int dg = 0; dg < 4; dg++) {
                unsigned vh[4];
                uint32_t voff = ((kt * 16 + lm_r) * 72 + dg * 16 + lm_c) * 2;
                ldsm4t(vh, uV + voff);
                mma_f16(oacc[2 * dg],     ph[kt], &vh[0]);
                mma_f16(oacc[2 * dg + 1], ph[kt], &vh[2]);
            }
        }
        __syncthreads();
    }

    // normalize + store O (single fp16)
    float inv1 = 1.0f / l1, inv2 = 1.0f / l2;
    int r1 = q0 + w * 16 + (lane >> 2);
#pragma unroll
    for (int nt = 0; nt < 8; nt++) {
        int d = nt * 8 + (lane & 3) * 2;
        size_t off = ((size_t)(b * SS + r1)) * EE + h * DD + d;
        *(unsigned*)&g_o16[off] = pack_h2(oacc[nt][0] * inv1, oacc[nt][1] * inv1);
        off = ((size_t)(b * SS + r1 + 8)) * EE + h * DD + d;
        *(unsigned*)&g_o16[off] = pack_h2(oacc[nt][2] * inv2, oacc[nt][3] * inv2);
    }
}

// ---------------------------------------------------------------------------
extern "C" void kernel_launch(void* const* d_in, const int* in_sizes, int n_in,
                              void* d_out, int out_size) {
    const float* x = (const float*)d_in[0];      // (B, S, E)
    const float* w_qkv = (const float*)d_in[1];  // (E, 3E)
    const float* w_out = (const float*)d_in[2];  // (E, E)
    float* out = (float*)d_out;                  // (B, S, E)

    __half *p_x, *p_wq, *p_wo, *p_o;
    cudaGetSymbolAddress((void**)&p_x, g_x16);
    cudaGetSymbolAddress((void**)&p_wq, g_wq16);
    cudaGetSymbolAddress((void**)&p_wo, g_wo16);
    cudaGetSymbolAddress((void**)&p_o, g_o16);

    // 0) convert inputs once
    conv_kernel<<<(BB*SS*EE/4 + 255) / 256, 256>>>(x, p_x, BB*SS*EE/4);
    conv_kernel<<<(EE*NQKV/4 + 255) / 256, 256>>>(w_qkv, p_wq, EE*NQKV/4);
    conv_kernel<<<(EE*EE/4 + 255) / 256, 256>>>(w_out, p_wo, EE*EE/4);

    // 1) QKV projection, scatter Q/K/V (Q pre-scaled by 0.125*log2e)
    cudaFuncSetAttribute(mma_gemm4<NQKV, true>,
                         cudaFuncAttributeMaxDynamicSharedMemorySize, G4_SMEM);
    mma_gemm4<NQKV, true><<<dim3(NQKV / 128, (BB * SS) / 128), 256, G4_SMEM>>>(
        p_x, p_wq, nullptr);

    // 2) Flash attention
    const int attn_smem = (AT_Q + 4 * AT_T) * (int)sizeof(__half);
    cudaFuncSetAttribute(attn_mma4, cudaFuncAttributeMaxDynamicSharedMemorySize,
                         attn_smem);
    attn_mma4<<<dim3(SS / 128, HH, BB), 256, attn_smem>>>();

    // 3) Output projection
    cudaFuncSetAttribute(mma_gemm4<EE, false>,
                         cudaFuncAttributeMaxDynamicSharedMemorySize, G4_SMEM);
    mma_gemm4<EE, false><<<dim3(EE / 128, (BB * SS) / 128), 256, G4_SMEM>>>(
        p_o, p_wo, out);
}

// round 12
// speedup vs baseline: 2.4478x; 1.0472x over previous
#include <cuda_runtime.h>
#include <cuda_fp16.h>
#include <cstdint>
#include <math.h>

#define BB 2
#define SS 2048
#define EE 1024
#define HH 16
#define DD 64
#define NQKV 3072

// ---------------------------------------------------------------------------
// Scratch (device globals — allocation-free). Plain fp16 everywhere.
// ---------------------------------------------------------------------------
__device__ __half g_x16[BB*SS*EE];       // x
__device__ __half g_wq16[EE*NQKV];       // w_qkv
__device__ __half g_wo16[EE*EE];         // w_out
__device__ __half g_q16[BB*HH*SS*DD];    // Q (pre-scaled by 0.125*log2e)
__device__ __half g_k16[BB*HH*SS*DD];
__device__ __half g_v16[BB*HH*SS*DD];
__device__ __half g_o16[BB*SS*EE];       // attention output

// single TU-wide dynamic smem symbol (char) — cast per kernel
extern __shared__ __align__(16) char dynsmem[];

// ---------------------------------------------------------------------------
// PTX wrappers
// ---------------------------------------------------------------------------
__device__ __forceinline__ void ldsm4(unsigned r[4], uint32_t a) {
    asm volatile("ldmatrix.sync.aligned.m8n8.x4.shared.b16 {%0,%1,%2,%3}, [%4];\n"
                 : "=r"(r[0]), "=r"(r[1]), "=r"(r[2]), "=r"(r[3]) : "r"(a));
}
__device__ __forceinline__ void ldsm4t(unsigned r[4], uint32_t a) {
    asm volatile("ldmatrix.sync.aligned.m8n8.x4.trans.shared.b16 {%0,%1,%2,%3}, [%4];\n"
                 : "=r"(r[0]), "=r"(r[1]), "=r"(r[2]), "=r"(r[3]) : "r"(a));
}
__device__ __forceinline__ void mma_f16(float c[4], const unsigned a[4], const unsigned b[2]) {
    asm volatile(
        "mma.sync.aligned.m16n8k16.row.col.f32.f16.f16.f32 "
        "{%0,%1,%2,%3}, {%4,%5,%6,%7}, {%8,%9}, {%0,%1,%2,%3};\n"
        : "+f"(c[0]), "+f"(c[1]), "+f"(c[2]), "+f"(c[3])
        : "r"(a[0]), "r"(a[1]), "r"(a[2]), "r"(a[3]), "r"(b[0]), "r"(b[1]));
}
__device__ __forceinline__ void cp16(uint32_t s, const void* g) {
    asm volatile("cp.async.cg.shared.global [%0], [%1], 16;\n" :: "r"(s), "l"(g));
}
__device__ __forceinline__ void cp_commit() {
    asm volatile("cp.async.commit_group;\n" ::: "memory");
}
template <int N>
__device__ __forceinline__ void cp_wait() {
    asm volatile("cp.async.wait_group %0;\n" :: "n"(N) : "memory");
}
__device__ __forceinline__ unsigned pack_h2(float x, float y) {
    __half2 h2 = __floats2half2_rn(x, y);
    return *reinterpret_cast<unsigned*>(&h2);
}
// packed fp16 2^x (single MUFU instruction for two values)
__device__ __forceinline__ unsigned h2_ex2(unsigned in) {
    unsigned out;
    asm("ex2.approx.f16x2 %0, %1;" : "=r"(out) : "r"(in));
    return out;
}
__device__ __forceinline__ uint32_t smem_u32(const void* p) {
    return (uint32_t)__cvta_generic_to_shared(p);
}

// ---------------------------------------------------------------------------
// Elementwise fp32 -> fp16 convert
// ---------------------------------------------------------------------------
__global__ __launch_bounds__(256) void conv_kernel(const float* __restrict__ src,
                                                   __half* __restrict__ dst,
                                                   int n4) {
    int i = blockIdx.x * 256 + threadIdx.x;
    if (i < n4) {
        float4 v = *(const float4*)(src + (size_t)i * 4);
        *(uint2*)(dst + (size_t)i * 4) =
            make_uint2(pack_h2(v.x, v.y), pack_h2(v.z, v.w));
    }
}

// ---------------------------------------------------------------------------
// fp16 GEMM: C[M, NC] = A[M,1024] @ W[1024,NC]
// BM=128, BN=128, BK=64, 8 warps, warp tile 32x64, 2 CTAs/SM.
// 3-stage cp.async ring, depth-2 prefetch, 1 sync per 64-deep k-tile.
// Stage layout (elems): [A 128*72 | B 64*136]
// ---------------------------------------------------------------------------
#define ST_A 9216                          // 128*72 elems
#define ST_B 8704                          // 64*136 elems
#define ST_BYTES ((ST_A + ST_B) * 2)       // 35840 B
#define G5_SMEM (3 * ST_BYTES)             // 107520 B

template <int NC, bool SCATTER>
__global__ __launch_bounds__(256, 2) void mma_gemm5(const __half* __restrict__ A_g,
                                                    const __half* __restrict__ B_g,
                                                    float* __restrict__ C) {
    char* smem = dynsmem;
    const int tid = threadIdx.x;
    const int lane = tid & 31, wid = tid >> 5;
    const int wm = (wid & 3) * 32, wn = (wid >> 2) * 64;
    const int m0 = blockIdx.y * 128, n0 = blockIdx.x * 128;

    const uint32_t uS = smem_u32(smem);
    const int lm_r = lane & 15, lm_c = (lane >> 4) * 8;
    const uint32_t aoff0 = ((wm + lm_r) * 72 + lm_c) * 2;
    const uint32_t boff0 = (lm_r * 136 + wn + lm_c) * 2;

    float acc[2][8][4];
#pragma unroll
    for (int i = 0; i < 2; i++)
#pragma unroll
        for (int j = 0; j < 8; j++)
#pragma unroll
            for (int q = 0; q < 4; q++) acc[i][j][q] = 0.0f;

    auto load_tile = [&](int slot, int k0) {
        uint32_t base = uS + slot * ST_BYTES;
        // A: 128 x 64 = 8192 elems -> 1024 cp16 -> 4 per thread
#pragma unroll
        for (int i = 0; i < 4; i++) {
            int idx = tid + i * 256;              // 0..1023
            int r = idx >> 3, c8 = (idx & 7) * 8; // r 0..127, c8 0..56
            cp16(base + (r * 72 + c8) * 2,
                 A_g + (size_t)(m0 + r) * EE + k0 + c8);
        }
        uint32_t bbase = base + ST_A * 2;
        // B: 64 x 128 = 8192 elems -> 4 per thread
#pragma unroll
        for (int i = 0; i < 4; i++) {
            int idx = tid + i * 256;
            int r = idx >> 4, c8 = (idx & 15) * 8; // r 0..63, c8 0..120
            cp16(bbase + (r * 136 + c8) * 2,
                 B_g + (size_t)(k0 + r) * NC + n0 + c8);
        }
    };

    load_tile(0, 0);  cp_commit();
    load_tile(1, 64); cp_commit();

    int slot = 0, pslot = 2;
#pragma unroll 1
    for (int kt = 0; kt < 16; kt++) {
        if (kt < 15) cp_wait<1>(); else cp_wait<0>();
        __syncthreads();

        if (kt + 2 < 16) {
            load_tile(pslot, (kt + 2) * 64);
            cp_commit();
        }

        const uint32_t uA = uS + slot * ST_BYTES;
        const uint32_t uB = uA + ST_A * 2;

#pragma unroll
        for (int ks = 0; ks < 4; ks++) {
            const int kk = ks * 16;
            unsigned ah[2][4];
#pragma unroll
            for (int tm = 0; tm < 2; tm++) {
                uint32_t off = aoff0 + (tm * 16 * 72 + kk) * 2;
                ldsm4(ah[tm], uA + off);
            }
#pragma unroll
            for (int g = 0; g < 4; g++) {
                unsigned bh[4];
                uint32_t off = boff0 + (kk * 136 + g * 16) * 2;
                ldsm4t(bh, uB + off);
                mma_f16(acc[0][2 * g],     ah[0], &bh[0]);
                mma_f16(acc[0][2 * g + 1], ah[0], &bh[2]);
                mma_f16(acc[1][2 * g],     ah[1], &bh[0]);
                mma_f16(acc[1][2 * g + 1], ah[1], &bh[2]);
            }
        }
        slot = (slot == 2) ? 0 : slot + 1;
        pslot = (pslot == 2) ? 0 : pslot + 1;
    }

    if (SCATTER) {
        const float LOG2E_SC = 0.125f * 1.44269504088896340736f;
#pragma unroll
        for (int tm = 0; tm < 2; tm++)
#pragma unroll
            for (int nt = 0; nt < 8; nt++) {
                int f = n0 + wn + nt * 8 + (lane & 3) * 2;
                int cid = f >> 10;
                int hh = (f >> 6) & (HH - 1);
                int d = f & (DD - 1);
                float sc = (cid == 0) ? LOG2E_SC : 1.0f;   // Q scaled for log2-domain softmax
                __half* dst = (cid == 0) ? g_q16 : (cid == 1) ? g_k16 : g_v16;
#pragma unroll
                for (int half = 0; half < 2; half++) {
                    int row = m0 + wm + tm * 16 + (lane >> 2) + half * 8;
                    int b = row >> 11, s = row & (SS - 1);
                    size_t off = ((size_t)((b * HH + hh) * SS + s)) * DD + d;
                    *(unsigned*)&dst[off] = pack_h2(acc[tm][nt][half * 2] * sc,
                                                    acc[tm][nt][half * 2 + 1] * sc);
                }
            }
    } else {
#pragma unroll
        for (int tm = 0; tm < 2; tm++)
#pragma unroll
            for (int nt = 0; nt < 8; nt++) {
                int col = n0 + wn + nt * 8 + (lane & 3) * 2;
#pragma unroll
                for (int half = 0; half < 2; half++) {
                    int row = m0 + wm + tm * 16 + (lane >> 2) + half * 8;
                    float2 v = make_float2(acc[tm][nt][half * 2],
                                           acc[tm][nt][half * 2 + 1]);
                    *(float2*)&C[(size_t)row * NC + col] = v;
                }
            }
    }
}

// ---------------------------------------------------------------------------
// Flash attention, fp16 mma, log2-domain softmax with fp16 ex2.
// CTA = (b, h, 128 q rows), 8 warps, kv tiles of 64, 4-buffer cp.async ring
// (depth-2 prefetch), 2 CTAs/SM. Q fragments hoisted out of the kv loop.
// Row sums via MMA against a constant ones B-fragment.
// smem elems: Q[128*72] + 4 bufs x (K[64*72] + V[64*72])
// ---------------------------------------------------------------------------
#define AT_Q 9216            // 128*72 elems
#define AT_T 4608            // 64*72 elems

__global__ __launch_bounds__(256, 2) void attn_mma5() {
    __half* smem = (__half*)dynsmem;
    const int tid = threadIdx.x, lane = tid & 31, w = tid >> 5;
    const int q0 = blockIdx.x * 128, h = blockIdx.y, b = blockIdx.z;
    const size_t hb = (size_t)(b * HH + h) * SS * DD;

    const uint32_t uS = smem_u32(smem);
    const uint32_t uQ = uS;

    const int lm_r = lane & 15, lm_c = (lane >> 4) * 8;
    const int bn_r = (lane & 7) + (lane >> 4) * 8;
    const int bn_c = ((lane >> 3) & 1) * 8;

    // Constant B fragment for row-sum MMA: B[k][0] = 1 for all k, else 0.
    unsigned bones[2];
    bones[0] = bones[1] = (lane < 4) ? 0x3C003C00u : 0u;

    auto kv_base = [&](int buf, int t) -> uint32_t {
        return uS + (AT_Q + (buf * 2 + t) * AT_T) * 2;
    };

    auto load_kv = [&](int buf, int kv) {
        const __half* s0 = g_k16 + hb + (size_t)kv * DD;
        const __half* s1 = g_v16 + hb + (size_t)kv * DD;
#pragma unroll
        for (int i = 0; i < 2; i++) {
            int idx = tid + i * 256;
            int r = idx >> 3, c8 = (idx & 7) * 8;
            uint32_t so = (r * 72 + c8) * 2;
            int go = r * DD + c8;
            cp16(kv_base(buf, 0) + so, s0 + go);
            cp16(kv_base(buf, 1) + so, s1 + go);
        }
    };

    // group 0: Q + KV tile 0; groups 1,2: KV tiles 1,2
#pragma unroll
    for (int i = 0; i < 4; i++) {
        int idx = tid + i * 256;
        int r = idx >> 3, c8 = (idx & 7) * 8;
        uint32_t so = (r * 72 + c8) * 2;
        size_t go = hb + (size_t)(q0 + r) * DD + c8;
        cp16(uQ + so, g_q16 + go);
    }
    load_kv(0, 0);   cp_commit();
    load_kv(1, 64);  cp_commit();
    load_kv(2, 128); cp_commit();

    // m in log2 domain
    float m1 = -1.0e30f, m2 = -1.0e30f, l1 = 0.0f, l2 = 0.0f;
    float oacc[8][4];
#pragma unroll
    for (int j = 0; j < 8; j++)
#pragma unroll
        for (int q = 0; q < 4; q++) oacc[j][q] = 0.0f;

    unsigned aq[4][4];   // hoisted Q fragments (loaded at ti==0)

#pragma unroll 1
    for (int ti = 0; ti < 32; ti++) {
        const int buf = ti & 3;
        if (ti < 30) cp_wait<2>();
        else if (ti == 30) cp_wait<1>();
        else cp_wait<0>();
        __syncthreads();

        if (ti + 3 < 32) {
            load_kv((ti + 3) & 3, (ti + 3) * 64);
            cp_commit();
        }

        if (ti == 0) {
#pragma unroll
            for (int kt = 0; kt < 4; kt++) {
                uint32_t qoff = ((w * 16 + lm_r) * 72 + kt * 16 + lm_c) * 2;
                ldsm4(aq[kt], uQ + qoff);
            }
        }

        const uint32_t uK = kv_base(buf, 0);
        const uint32_t uV = kv_base(buf, 1);

        // S = Q @ K^T  (log2e * scale folded into Q)
        float sacc[8][4];
#pragma unroll
        for (int j = 0; j < 8; j++)
#pragma unroll
            for (int q = 0; q < 4; q++) sacc[j][q] = 0.0f;

#pragma unroll
        for (int kt = 0; kt < 4; kt++) {
#pragma unroll
            for (int g = 0; g < 4; g++) {
                unsigned bh[4];
                uint32_t koff = ((g * 16 + bn_r) * 72 + kt * 16 + bn_c) * 2;
                ldsm4(bh, uK + koff);
                mma_f16(sacc[2 * g],     aq[kt], &bh[0]);
                mma_f16(sacc[2 * g + 1], aq[kt], &bh[2]);
            }
        }

        // Row max (log2 domain)
        float mx1 = -1.0e30f, mx2 = -1.0e30f;
#pragma unroll
        for (int nt = 0; nt < 8; nt++) {
            mx1 = fmaxf(mx1, fmaxf(sacc[nt][0], sacc[nt][1]));
            mx2 = fmaxf(mx2, fmaxf(sacc[nt][2], sacc[nt][3]));
        }
#pragma unroll
        for (int off = 1; off <= 2; off <<= 1) {
            mx1 = fmaxf(mx1, __shfl_xor_sync(0xffffffffu, mx1, off));
            mx2 = fmaxf(mx2, __shfl_xor_sync(0xffffffffu, mx2, off));
        }
        float mn1 = fmaxf(m1, mx1), mn2 = fmaxf(m2, mx2);
        float fac1 = exp2f(m1 - mn1), fac2 = exp2f(m2 - mn2);
        m1 = mn1;
        m2 = mn2;

        // P = 2^(S - mn) in packed fp16 via ex2.approx.f16x2
        unsigned ph[4][4];
#pragma unroll
        for (int kt = 0; kt < 4; kt++) {
            ph[kt][0] = h2_ex2(pack_h2(sacc[2 * kt][0] - mn1,     sacc[2 * kt][1] - mn1));
            ph[kt][1] = h2_ex2(pack_h2(sacc[2 * kt][2] - mn2,     sacc[2 * kt][3] - mn2));
            ph[kt][2] = h2_ex2(pack_h2(sacc[2 * kt + 1][0] - mn1, sacc[2 * kt + 1][1] - mn1));
            ph[kt][3] = h2_ex2(pack_h2(sacc[2 * kt + 1][2] - mn2, sacc[2 * kt + 1][3] - mn2));
        }

        // Row sums via MMA with constant ones-fragment
        float racc[4] = {0.0f, 0.0f, 0.0f, 0.0f};
#pragma unroll
        for (int kt = 0; kt < 4; kt++) mma_f16(racc, ph[kt], bones);
        float rs1 = __shfl_sync(0xffffffffu, racc[0], 0, 4);
        float rs2 = __shfl_sync(0xffffffffu, racc[2], 0, 4);

        l1 = l1 * fac1 + rs1;
        l2 = l2 * fac2 + rs2;
#pragma unroll
        for (int nt = 0; nt < 8; nt++) {
            oacc[nt][0] *= fac1;
            oacc[nt][1] *= fac1;
            oacc[nt][2] *= fac2;
            oacc[nt][3] *= fac2;
        }

        // O += P @ V
#pragma unroll
        for (int kt = 0; kt < 4; kt++) {
#pragma unroll
            for (int dg = 0; dg < 4; dg++) {
                unsigned vh[4];
                uint32_t voff = ((kt * 16 + lm_r) * 72 + dg * 16 + lm_c) * 2;
                ldsm4t(vh, uV + voff);
                mma_f16(oacc[2 * dg],     ph[kt], &vh[0]);
                mma_f16(oacc[2 * dg + 1], ph[kt], &vh[2]);
            }
        }
        __syncthreads();
    }

    // normalize + store O (single fp16)
    float inv1 = 1.0f / l1, inv2 = 1.0f / l2;
    int r1 = q0 + w * 16 + (lane >> 2);
#pragma unroll
    for (int nt = 0; nt < 8; nt++) {
        int d = nt * 8 + (lane & 3) * 2;
        size_t off = ((size_t)(b * SS + r1)) * EE + h * DD + d;
        *(unsigned*)&g_o16[off] = pack_h2(oacc[nt][0] * inv1, oacc[nt][1] * inv1);
        off = ((size_t)(b * SS + r1 + 8)) * EE + h * DD + d;
        *(unsigned*)&g_o16[off] = pack_h2(oacc[nt][2] * inv2, oacc[nt][3] * inv2);
    }
}

// ---------------------------------------------------------------------------
extern "C" void kernel_launch(void* const* d_in, const int* in_sizes, int n_in,
                              void* d_out, int out_size) {
    const float* x = (const float*)d_in[0];      // (B, S, E)
    const float* w_qkv = (const float*)d_in[1];  // (E, 3E)
    const float* w_out = (const float*)d_in[2];  // (E, E)
    float* out = (float*)d_out;                  // (B, S, E)

    __half *p_x, *p_wq, *p_wo, *p_o;
    cudaGetSymbolAddress((void**)&p_x, g_x16);
    cudaGetSymbolAddress((void**)&p_wq, g_wq16);
    cudaGetSymbolAddress((void**)&p_wo, g_wo16);
    cudaGetSymbolAddress((void**)&p_o, g_o16);

    // 0) convert inputs once
    conv_kernel<<<(BB*SS*EE/4 + 255) / 256, 256>>>(x, p_x, BB*SS*EE/4);
    conv_kernel<<<(EE*NQKV/4 + 255) / 256, 256>>>(w_qkv, p_wq, EE*NQKV/4);
    conv_kernel<<<(EE*EE/4 + 255) / 256, 256>>>(w_out, p_wo, EE*EE/4);

    // 1) QKV projection, scatter Q/K/V (Q pre-scaled by 0.125*log2e)
    cudaFuncSetAttribute(mma_gemm5<NQKV, true>,
                         cudaFuncAttributeMaxDynamicSharedMemorySize, G5_SMEM);
    mma_gemm5<NQKV, true><<<dim3(NQKV / 128, (BB * SS) / 128), 256, G5_SMEM>>>(
        p_x, p_wq, nullptr);

    // 2) Flash attention
    const int attn_smem = (AT_Q + 8 * AT_T) * (int)sizeof(__half);
    cudaFuncSetAttribute(attn_mma5, cudaFuncAttributeMaxDynamicSharedMemorySize,
                         attn_smem);
    attn_mma5<<<dim3(SS / 128, HH, BB), 256, attn_smem>>>();

    // 3) Output projection
    cudaFuncSetAttribute(mma_gemm5<EE, false>,
                         cudaFuncAttributeMaxDynamicSharedMemorySize, G5_SMEM);
    mma_gemm5<EE, false><<<dim3(EE / 128, (BB * SS) / 128), 256, G5_SMEM>>>(
        p_o, p_wo, out);
}

// round 13
// speedup vs baseline: 2.5546x; 1.0436x over previous
#include <cuda_runtime.h>
#include <cuda_fp16.h>
#include <cstdint>
#include <math.h>

#define BB 2
#define SS 2048
#define EE 1024
#define HH 16
#define DD 64
#define NQKV 3072

// ---------------------------------------------------------------------------
// Scratch (device globals — allocation-free). Plain fp16 everywhere.
// ---------------------------------------------------------------------------
__device__ __half g_x16[BB*SS*EE];       // x
__device__ __half g_wq16[EE*NQKV];       // w_qkv
__device__ __half g_wo16[EE*EE];         // w_out
__device__ __half g_q16[BB*HH*SS*DD];    // Q (pre-scaled by 0.125*log2e)
__device__ __half g_k16[BB*HH*SS*DD];
__device__ __half g_v16[BB*HH*SS*DD];
__device__ __half g_o16[BB*SS*EE];       // attention output

// single TU-wide dynamic smem symbol (char) — cast per kernel
extern __shared__ __align__(16) char dynsmem[];

// ---------------------------------------------------------------------------
// PTX wrappers
// ---------------------------------------------------------------------------
__device__ __forceinline__ void ldsm4(unsigned r[4], uint32_t a) {
    asm volatile("ldmatrix.sync.aligned.m8n8.x4.shared.b16 {%0,%1,%2,%3}, [%4];\n"
                 : "=r"(r[0]), "=r"(r[1]), "=r"(r[2]), "=r"(r[3]) : "r"(a));
}
__device__ __forceinline__ void ldsm4t(unsigned r[4], uint32_t a) {
    asm volatile("ldmatrix.sync.aligned.m8n8.x4.trans.shared.b16 {%0,%1,%2,%3}, [%4];\n"
                 : "=r"(r[0]), "=r"(r[1]), "=r"(r[2]), "=r"(r[3]) : "r"(a));
}
__device__ __forceinline__ void mma_f16(float c[4], const unsigned a[4], const unsigned b[2]) {
    asm volatile(
        "mma.sync.aligned.m16n8k16.row.col.f32.f16.f16.f32 "
        "{%0,%1,%2,%3}, {%4,%5,%6,%7}, {%8,%9}, {%0,%1,%2,%3};\n"
        : "+f"(c[0]), "+f"(c[1]), "+f"(c[2]), "+f"(c[3])
        : "r"(a[0]), "r"(a[1]), "r"(a[2]), "r"(a[3]), "r"(b[0]), "r"(b[1]));
}
__device__ __forceinline__ void cp16(uint32_t s, const void* g) {
    asm volatile("cp.async.cg.shared.global [%0], [%1], 16;\n" :: "r"(s), "l"(g));
}
__device__ __forceinline__ void cp_commit() {
    asm volatile("cp.async.commit_group;\n" ::: "memory");
}
template <int N>
__device__ __forceinline__ void cp_wait() {
    asm volatile("cp.async.wait_group %0;\n" :: "n"(N) : "memory");
}
__device__ __forceinline__ unsigned pack_h2(float x, float y) {
    __half2 h2 = __floats2half2_rn(x, y);
    return *reinterpret_cast<unsigned*>(&h2);
}
__device__ __forceinline__ unsigned h2_ex2(unsigned in) {
    unsigned out;
    asm("ex2.approx.f16x2 %0, %1;" : "=r"(out) : "r"(in));
    return out;
}
__device__ __forceinline__ uint32_t smem_u32(const void* p) {
    return (uint32_t)__cvta_generic_to_shared(p);
}

// ---------------------------------------------------------------------------
// Merged fp32 -> fp16 convert for x, w_qkv, w_out (single launch)
// ---------------------------------------------------------------------------
#define CN1 (BB*SS*EE/4)
#define CN2 (EE*NQKV/4)
#define CN3 (EE*EE/4)

__global__ __launch_bounds__(256) void conv3_kernel(const float* __restrict__ s1,
                                                    const float* __restrict__ s2,
                                                    const float* __restrict__ s3,
                                                    __half* __restrict__ d1,
                                                    __half* __restrict__ d2,
                                                    __half* __restrict__ d3) {
    int i = blockIdx.x * 256 + threadIdx.x;
    const float* src;
    __half* dst;
    int j;
    if (i < CN1)              { src = s1; dst = d1; j = i; }
    else if (i < CN1 + CN2)   { src = s2; dst = d2; j = i - CN1; }
    else if (i < CN1+CN2+CN3) { src = s3; dst = d3; j = i - CN1 - CN2; }
    else return;
    float4 v = *(const float4*)(src + (size_t)j * 4);
    *(uint2*)(dst + (size_t)j * 4) =
        make_uint2(pack_h2(v.x, v.y), pack_h2(v.z, v.w));
}

// ---------------------------------------------------------------------------
// fp16 GEMM: C[M, NC] = A[M,1024] @ W[1024,NC]   (unchanged from round 12)
// BM=128, BN=128, BK=64, 8 warps, warp tile 32x64, 2 CTAs/SM.
// ---------------------------------------------------------------------------
#define ST_A 9216                          // 128*72 elems
#define ST_B 8704                          // 64*136 elems
#define ST_BYTES ((ST_A + ST_B) * 2)       // 35840 B
#define G5_SMEM (3 * ST_BYTES)             // 107520 B

template <int NC, bool SCATTER>
__global__ __launch_bounds__(256, 2) void mma_gemm5(const __half* __restrict__ A_g,
                                                    const __half* __restrict__ B_g,
                                                    float* __restrict__ C) {
    char* smem = dynsmem;
    const int tid = threadIdx.x;
    const int lane = tid & 31, wid = tid >> 5;
    const int wm = (wid & 3) * 32, wn = (wid >> 2) * 64;
    const int m0 = blockIdx.y * 128, n0 = blockIdx.x * 128;

    const uint32_t uS = smem_u32(smem);
    const int lm_r = lane & 15, lm_c = (lane >> 4) * 8;
    const uint32_t aoff0 = ((wm + lm_r) * 72 + lm_c) * 2;
    const uint32_t boff0 = (lm_r * 136 + wn + lm_c) * 2;

    float acc[2][8][4];
#pragma unroll
    for (int i = 0; i < 2; i++)
#pragma unroll
        for (int j = 0; j < 8; j++)
#pragma unroll
            for (int q = 0; q < 4; q++) acc[i][j][q] = 0.0f;

    auto load_tile = [&](int slot, int k0) {
        uint32_t base = uS + slot * ST_BYTES;
#pragma unroll
        for (int i = 0; i < 4; i++) {
            int idx = tid + i * 256;
            int r = idx >> 3, c8 = (idx & 7) * 8;
            cp16(base + (r * 72 + c8) * 2,
                 A_g + (size_t)(m0 + r) * EE + k0 + c8);
        }
        uint32_t bbase = base + ST_A * 2;
#pragma unroll
        for (int i = 0; i < 4; i++) {
            int idx = tid + i * 256;
            int r = idx >> 4, c8 = (idx & 15) * 8;
            cp16(bbase + (r * 136 + c8) * 2,
                 B_g + (size_t)(k0 + r) * NC + n0 + c8);
        }
    };

    load_tile(0, 0);  cp_commit();
    load_tile(1, 64); cp_commit();

    int slot = 0, pslot = 2;
#pragma unroll 1
    for (int kt = 0; kt < 16; kt++) {
        if (kt < 15) cp_wait<1>(); else cp_wait<0>();
        __syncthreads();

        if (kt + 2 < 16) {
            load_tile(pslot, (kt + 2) * 64);
            cp_commit();
        }

        const uint32_t uA = uS + slot * ST_BYTES;
        const uint32_t uB = uA + ST_A * 2;

#pragma unroll
        for (int ks = 0; ks < 4; ks++) {
            const int kk = ks * 16;
            unsigned ah[2][4];
#pragma unroll
            for (int tm = 0; tm < 2; tm++) {
                uint32_t off = aoff0 + (tm * 16 * 72 + kk) * 2;
                ldsm4(ah[tm], uA + off);
            }
#pragma unroll
            for (int g = 0; g < 4; g++) {
                unsigned bh[4];
                uint32_t off = boff0 + (kk * 136 + g * 16) * 2;
                ldsm4t(bh, uB + off);
                mma_f16(acc[0][2 * g],     ah[0], &bh[0]);
                mma_f16(acc[0][2 * g + 1], ah[0], &bh[2]);
                mma_f16(acc[1][2 * g],     ah[1], &bh[0]);
                mma_f16(acc[1][2 * g + 1], ah[1], &bh[2]);
            }
        }
        slot = (slot == 2) ? 0 : slot + 1;
        pslot = (pslot == 2) ? 0 : pslot + 1;
    }

    if (SCATTER) {
        const float LOG2E_SC = 0.125f * 1.44269504088896340736f;
#pragma unroll
        for (int tm = 0; tm < 2; tm++)
#pragma unroll
            for (int nt = 0; nt < 8; nt++) {
                int f = n0 + wn + nt * 8 + (lane & 3) * 2;
                int cid = f >> 10;
                int hh = (f >> 6) & (HH - 1);
                int d = f & (DD - 1);
                float sc = (cid == 0) ? LOG2E_SC : 1.0f;
                __half* dst = (cid == 0) ? g_q16 : (cid == 1) ? g_k16 : g_v16;
#pragma unroll
                for (int half = 0; half < 2; half++) {
                    int row = m0 + wm + tm * 16 + (lane >> 2) + half * 8;
                    int b = row >> 11, s = row & (SS - 1);
                    size_t off = ((size_t)((b * HH + hh) * SS + s)) * DD + d;
                    *(unsigned*)&dst[off] = pack_h2(acc[tm][nt][half * 2] * sc,
                                                    acc[tm][nt][half * 2 + 1] * sc);
                }
            }
    } else {
#pragma unroll
        for (int tm = 0; tm < 2; tm++)
#pragma unroll
            for (int nt = 0; nt < 8; nt++) {
                int col = n0 + wn + nt * 8 + (lane & 3) * 2;
#pragma unroll
                for (int half = 0; half < 2; half++) {
                    int row = m0 + wm + tm * 16 + (lane >> 2) + half * 8;
                    float2 v = make_float2(acc[tm][nt][half * 2],
                                           acc[tm][nt][half * 2 + 1]);
                    *(float2*)&C[(size_t)row * NC + col] = v;
                }
            }
    }
}

// ---------------------------------------------------------------------------
// Flash attention v6: M_w=32 (4 warps x 32 q rows per 128-row CTA),
// 128 threads, 3 CTAs/SM. fp16 mma, log2-domain softmax with fp16 ex2,
// rowsum via ones-fragment MMA. 3-buffer KV cp.async ring (depth 2).
// smem elems: Q[128*72] + 3 bufs x (K[64*72] + V[64*72]) = 73728 B
// ---------------------------------------------------------------------------
#define AT_Q 9216            // 128*72 elems
#define AT_T 4608            // 64*72 elems
#define AT6_SMEM ((AT_Q + 6 * AT_T) * 2)

__global__ __launch_bounds__(128, 3) void attn_mma6() {
    __half* smem = (__half*)dynsmem;
    const int tid = threadIdx.x, lane = tid & 31, w = tid >> 5;   // w 0..3
    const int q0 = blockIdx.x * 128, h = blockIdx.y, b = blockIdx.z;
    const size_t hb = (size_t)(b * HH + h) * SS * DD;

    const uint32_t uS = smem_u32(smem);
    const uint32_t uQ = uS;

    const int lm_r = lane & 15, lm_c = (lane >> 4) * 8;
    const int bn_r = (lane & 7) + (lane >> 4) * 8;
    const int bn_c = ((lane >> 3) & 1) * 8;

    unsigned bones[2];
    bones[0] = bones[1] = (lane < 4) ? 0x3C003C00u : 0u;

    auto kv_base = [&](int buf, int t) -> uint32_t {
        return uS + (AT_Q + (buf * 2 + t) * AT_T) * 2;
    };

    auto load_kv = [&](int buf, int kv) {
        const __half* s0 = g_k16 + hb + (size_t)kv * DD;
        const __half* s1 = g_v16 + hb + (size_t)kv * DD;
#pragma unroll
        for (int i = 0; i < 4; i++) {
            int idx = tid + i * 128;               // 0..511
            int r = idx >> 3, c8 = (idx & 7) * 8;  // r 0..63
            uint32_t so = (r * 72 + c8) * 2;
            int go = r * DD + c8;
            cp16(kv_base(buf, 0) + so, s0 + go);
            cp16(kv_base(buf, 1) + so, s1 + go);
        }
    };

    // Q load (128x64) + first two KV tiles
#pragma unroll
    for (int i = 0; i < 8; i++) {
        int idx = tid + i * 128;                   // 0..1023
        int r = idx >> 3, c8 = (idx & 7) * 8;      // r 0..127
        uint32_t so = (r * 72 + c8) * 2;
        size_t go = hb + (size_t)(q0 + r) * DD + c8;
        cp16(uQ + so, g_q16 + go);
    }
    load_kv(0, 0);  cp_commit();
    load_kv(1, 64); cp_commit();

    // per-warp rows: [w*32, w*32+32). Row groups (per tm): lane>>2 and +8.
    float m[4], l[4];
#pragma unroll
    for (int i = 0; i < 4; i++) { m[i] = -1.0e30f; l[i] = 0.0f; }
    float oacc[2][8][4];
#pragma unroll
    for (int tm = 0; tm < 2; tm++)
#pragma unroll
        for (int j = 0; j < 8; j++)
#pragma unroll
            for (int q = 0; q < 4; q++) oacc[tm][j][q] = 0.0f;

    int slot = 0, pslot = 2;
#pragma unroll 1
    for (int ti = 0; ti < 32; ti++) {
        if (ti < 31) cp_wait<1>(); else cp_wait<0>();
        __syncthreads();

        if (ti + 2 < 32) {
            load_kv(pslot, (ti + 2) * 64);
            cp_commit();
        }

        const uint32_t uK = kv_base(slot, 0);
        const uint32_t uV = kv_base(slot, 1);

        // S = Q @ K^T for 32 q rows (2 m-tiles)
        float sacc[2][8][4];
#pragma unroll
        for (int tm = 0; tm < 2; tm++)
#pragma unroll
            for (int j = 0; j < 8; j++)
#pragma unroll
                for (int q = 0; q < 4; q++) sacc[tm][j][q] = 0.0f;

#pragma unroll
        for (int kt = 0; kt < 4; kt++) {
            unsigned aq[2][4];
#pragma unroll
            for (int tm = 0; tm < 2; tm++) {
                uint32_t qoff = ((w * 32 + tm * 16 + lm_r) * 72 + kt * 16 + lm_c) * 2;
                ldsm4(aq[tm], uQ + qoff);
            }
#pragma unroll
            for (int g = 0; g < 4; g++) {
                unsigned bh[4];
                uint32_t koff = ((g * 16 + bn_r) * 72 + kt * 16 + bn_c) * 2;
                ldsm4(bh, uK + koff);
                mma_f16(sacc[0][2 * g],     aq[0], &bh[0]);
                mma_f16(sacc[0][2 * g + 1], aq[0], &bh[2]);
                mma_f16(sacc[1][2 * g],     aq[1], &bh[0]);
                mma_f16(sacc[1][2 * g + 1], aq[1], &bh[2]);
            }
        }

        // Row max (log2 domain), 4 row groups
        float mn[4], fac[4];
#pragma unroll
        for (int tm = 0; tm < 2; tm++) {
            float mxa = -1.0e30f, mxb = -1.0e30f;
#pragma unroll
            for (int nt = 0; nt < 8; nt++) {
                mxa = fmaxf(mxa, fmaxf(sacc[tm][nt][0], sacc[tm][nt][1]));
                mxb = fmaxf(mxb, fmaxf(sacc[tm][nt][2], sacc[tm][nt][3]));
            }
#pragma unroll
            for (int off = 1; off <= 2; off <<= 1) {
                mxa = fmaxf(mxa, __shfl_xor_sync(0xffffffffu, mxa, off));
                mxb = fmaxf(mxb, __shfl_xor_sync(0xffffffffu, mxb, off));
            }
            mn[2 * tm]     = fmaxf(m[2 * tm], mxa);
            mn[2 * tm + 1] = fmaxf(m[2 * tm + 1], mxb);
            fac[2 * tm]     = exp2f(m[2 * tm] - mn[2 * tm]);
            fac[2 * tm + 1] = exp2f(m[2 * tm + 1] - mn[2 * tm + 1]);
            m[2 * tm] = mn[2 * tm];
            m[2 * tm + 1] = mn[2 * tm + 1];
        }

        // rescale O
#pragma unroll
        for (int tm = 0; tm < 2; tm++)
#pragma unroll
            for (int nt = 0; nt < 8; nt++) {
                oacc[tm][nt][0] *= fac[2 * tm];
                oacc[tm][nt][1] *= fac[2 * tm];
                oacc[tm][nt][2] *= fac[2 * tm + 1];
                oacc[tm][nt][3] *= fac[2 * tm + 1];
            }

        // per-kt: build P, rowsum, PV (keeps P transient)
        float racc[2][4] = {{0, 0, 0, 0}, {0, 0, 0, 0}};
#pragma unroll
        for (int kt = 0; kt < 4; kt++) {
            unsigned ph[2][4];
#pragma unroll
            for (int tm = 0; tm < 2; tm++) {
                ph[tm][0] = h2_ex2(pack_h2(sacc[tm][2 * kt][0] - mn[2 * tm],
                                           sacc[tm][2 * kt][1] - mn[2 * tm]));
                ph[tm][1] = h2_ex2(pack_h2(sacc[tm][2 * kt][2] - mn[2 * tm + 1],
                                           sacc[tm][2 * kt][3] - mn[2 * tm + 1]));
                ph[tm][2] = h2_ex2(pack_h2(sacc[tm][2 * kt + 1][0] - mn[2 * tm],
                                           sacc[tm][2 * kt + 1][1] - mn[2 * tm]));
                ph[tm][3] = h2_ex2(pack_h2(sacc[tm][2 * kt + 1][2] - mn[2 * tm + 1],
                                           sacc[tm][2 * kt + 1][3] - mn[2 * tm + 1]));
                mma_f16(racc[tm], ph[tm], bones);
            }
#pragma unroll
            for (int dg = 0; dg < 4; dg++) {
                unsigned vh[4];
                uint32_t voff = ((kt * 16 + lm_r) * 72 + dg * 16 + lm_c) * 2;
                ldsm4t(vh, uV + voff);                 // shared across both m-tiles
                mma_f16(oacc[0][2 * dg],     ph[0], &vh[0]);
                mma_f16(oacc[0][2 * dg + 1], ph[0], &vh[2]);
                mma_f16(oacc[1][2 * dg],     ph[1], &vh[0]);
                mma_f16(oacc[1][2 * dg + 1], ph[1], &vh[2]);
            }
        }

        // fold row sums into l
#pragma unroll
        for (int tm = 0; tm < 2; tm++) {
            float rsa = __shfl_sync(0xffffffffu, racc[tm][0], 0, 4);
            float rsb = __shfl_sync(0xffffffffu, racc[tm][2], 0, 4);
            l[2 * tm]     = l[2 * tm] * fac[2 * tm] + rsa;
            l[2 * tm + 1] = l[2 * tm + 1] * fac[2 * tm + 1] + rsb;
        }

        __syncthreads();
        slot = (slot == 2) ? 0 : slot + 1;
        pslot = (pslot == 2) ? 0 : pslot + 1;
    }

    // normalize + store O (single fp16)
#pragma unroll
    for (int tm = 0; tm < 2; tm++) {
        float inva = 1.0f / l[2 * tm], invb = 1.0f / l[2 * tm + 1];
        int r1 = q0 + w * 32 + tm * 16 + (lane >> 2);
#pragma unroll
        for (int nt = 0; nt < 8; nt++) {
            int d = nt * 8 + (lane & 3) * 2;
            size_t off = ((size_t)(b * SS + r1)) * EE + h * DD + d;
            *(unsigned*)&g_o16[off] = pack_h2(oacc[tm][nt][0] * inva,
                                              oacc[tm][nt][1] * inva);
            off = ((size_t)(b * SS + r1 + 8)) * EE + h * DD + d;
            *(unsigned*)&g_o16[off] = pack_h2(oacc[tm][nt][2] * invb,
                                              oacc[tm][nt][3] * invb);
        }
    }
}

// ---------------------------------------------------------------------------
extern "C" void kernel_launch(void* const* d_in, const int* in_sizes, int n_in,
                              void* d_out, int out_size) {
    const float* x = (const float*)d_in[0];      // (B, S, E)
    const float* w_qkv = (const float*)d_in[1];  // (E, 3E)
    const float* w_out = (const float*)d_in[2];  // (E, E)
    float* out = (float*)d_out;                  // (B, S, E)

    __half *p_x, *p_wq, *p_wo, *p_o;
    cudaGetSymbolAddress((void**)&p_x, g_x16);
    cudaGetSymbolAddress((void**)&p_wq, g_wq16);
    cudaGetSymbolAddress((void**)&p_wo, g_wo16);
    cudaGetSymbolAddress((void**)&p_o, g_o16);

    // 0) convert all inputs in one launch
    conv3_kernel<<<(CN1 + CN2 + CN3 + 255) / 256, 256>>>(x, w_qkv, w_out,
                                                         p_x, p_wq, p_wo);

    // 1) QKV projection, scatter Q/K/V (Q pre-scaled by 0.125*log2e)
    cudaFuncSetAttribute(mma_gemm5<NQKV, true>,
                         cudaFuncAttributeMaxDynamicSharedMemorySize, G5_SMEM);
    mma_gemm5<NQKV, true><<<dim3(NQKV / 128, (BB * SS) / 128), 256, G5_SMEM>>>(
        p_x, p_wq, nullptr);

    // 2) Flash attention (M_w=32, 128 threads, 3 CTAs/SM)
    cudaFuncSetAttribute(attn_mma6, cudaFuncAttributeMaxDynamicSharedMemorySize,
                         AT6_SMEM);
    attn_mma6<<<dim3(SS / 128, HH, BB), 128, AT6_SMEM>>>();

    // 3) Output projection
    cudaFuncSetAttribute(mma_gemm5<EE, false>,
                         cudaFuncAttributeMaxDynamicSharedMemorySize, G5_SMEM);
    mma_gemm5<EE, false><<<dim3(EE / 128, (BB * SS) / 128), 256, G5_SMEM>>>(
        p_o, p_wo, out);
}